// round 12
// baseline (speedup 1.0000x reference)
#include <cuda_runtime.h>
#include <cstdint>

#define D_IN 1024
#define HID  256
#define G4   1024
#define MID  512
#define SEQ  512
#define NB   4
#define NOUT 50
#define SED  64
#define NPOS 30
#define WLD  1090           // 2*(MID+1) + SED
#define ROWS 2048           // NB*SEQ
#define CPG  8              // CTAs per cluster
#define NCLUS 4             // clusters; each handles 2 groups (same dir)
#define UPC  32             // hidden units per CTA per group
#define HPAD 132            // floats per K-half (128 + 4 pad)
#define PSTR (2 * HPAD)     // floats per (group,parity) buffer

// ------------------------- scratch (static device memory) -------------------
__device__ float g_G[2][ROWS][G4];      // gate input preactivations (+bias)
__device__ float g_bias[2][G4];
__device__ float g_hcat[ROWS][MID];     // [b*SEQ+t][dir*HID + j]
__device__ float g_head[ROWS][MID];
__device__ float g_tail[ROWS][MID];
__device__ float g_shead[ROWS][NOUT];   // [(b,m)][k]
__device__ float g_stail[ROWS][NOUT];   // [(b,n)][k]
__device__ float g_sztab[NOUT][NPOS];

// ------------------------- prep: bias, size table ---------------------------
__global__ void prep_kernel(const float* __restrict__ bih_f, const float* __restrict__ bhh_f,
                            const float* __restrict__ bih_b, const float* __restrict__ bhh_b,
                            const float* __restrict__ emb,   const float* __restrict__ W)
{
    int g = blockIdx.x * blockDim.x + threadIdx.x;
    if (g < G4)            g_bias[0][g]      = bih_f[g]      + bhh_f[g];
    else if (g < 2 * G4)   g_bias[1][g - G4] = bih_b[g - G4] + bhh_b[g - G4];
    if (g < NOUT * NPOS) {
        int k = g / NPOS, p = g % NPOS;
        float s = 0.f;
        #pragma unroll 8
        for (int h = 0; h < SED; h++)
            s += emb[p * SED + h] * W[k * WLD + 2 * (MID + 1) + h];
        g_sztab[k][p] = s;
    }
}

// ------------------------- tf32 GEMM: C = A @ B^T (+bias, opt leaky) --------
__device__ __forceinline__ float to_tf32(float x) {
    uint32_t u;
    asm("cvt.rna.tf32.f32 %0, %1;" : "=r"(u) : "f"(x));
    return __uint_as_float(u);
}

__global__ void __launch_bounds__(128) gemm_tf32(
    const float* __restrict__ A, int lda,
    const float* __restrict__ Bw, int ldb,
    const float* __restrict__ bias, int bstr,
    float* __restrict__ C, int ldc,
    int N, int K, int act)
{
    __shared__ float As[64][33];
    __shared__ float Bs[64][33];
    int tid  = threadIdx.x;
    int warp = tid >> 5, lane = tid & 31;
    int gq = lane >> 2, tg = lane & 3;
    int wm = (warp >> 1) * 32, wn = (warp & 1) * 32;
    int bm = blockIdx.y * 64, bn = blockIdx.x * 64;

    float acc[2][4][4];
    #pragma unroll
    for (int a = 0; a < 2; a++)
        #pragma unroll
        for (int b = 0; b < 4; b++)
            #pragma unroll
            for (int c = 0; c < 4; c++) acc[a][b][c] = 0.f;

    bool bvec = ((ldb & 3) == 0);

    for (int k0 = 0; k0 < K; k0 += 32) {
        #pragma unroll
        for (int i = 0; i < 4; i++) {
            int l4 = tid + i * 128;
            int r = l4 >> 3, c4 = (l4 & 7) << 2;
            const float4 v = *reinterpret_cast<const float4*>(A + (size_t)(bm + r) * lda + k0 + c4);
            As[r][c4 + 0] = to_tf32(v.x); As[r][c4 + 1] = to_tf32(v.y);
            As[r][c4 + 2] = to_tf32(v.z); As[r][c4 + 3] = to_tf32(v.w);
        }
        #pragma unroll
        for (int i = 0; i < 4; i++) {
            int l4 = tid + i * 128;
            int r = l4 >> 3, c4 = (l4 & 7) << 2;
            float4 v;
            if (bn + r < N) {
                if (bvec) {
                    v = *reinterpret_cast<const float4*>(Bw + (size_t)(bn + r) * ldb + k0 + c4);
                } else {
                    const float* p = Bw + (size_t)(bn + r) * ldb + k0 + c4;
                    v = make_float4(p[0], p[1], p[2], p[3]);
                }
            } else v = make_float4(0.f, 0.f, 0.f, 0.f);
            Bs[r][c4 + 0] = to_tf32(v.x); Bs[r][c4 + 1] = to_tf32(v.y);
            Bs[r][c4 + 2] = to_tf32(v.z); Bs[r][c4 + 3] = to_tf32(v.w);
        }
        __syncthreads();

        #pragma unroll
        for (int kk = 0; kk < 32; kk += 8) {
            uint32_t af[2][4], bf[4][2];
            #pragma unroll
            for (int mf = 0; mf < 2; mf++) {
                int r0 = wm + mf * 16 + gq;
                af[mf][0] = __float_as_uint(As[r0    ][kk + tg]);
                af[mf][1] = __float_as_uint(As[r0 + 8][kk + tg]);
                af[mf][2] = __float_as_uint(As[r0    ][kk + tg + 4]);
                af[mf][3] = __float_as_uint(As[r0 + 8][kk + tg + 4]);
            }
            #pragma unroll
            for (int nf = 0; nf < 4; nf++) {
                int n0 = wn + nf * 8 + gq;
                bf[nf][0] = __float_as_uint(Bs[n0][kk + tg]);
                bf[nf][1] = __float_as_uint(Bs[n0][kk + tg + 4]);
            }
            #pragma unroll
            for (int mf = 0; mf < 2; mf++)
                #pragma unroll
                for (int nf = 0; nf < 4; nf++)
                    asm volatile(
                        "mma.sync.aligned.m16n8k8.row.col.f32.tf32.tf32.f32 "
                        "{%0,%1,%2,%3}, {%4,%5,%6,%7}, {%8,%9}, {%0,%1,%2,%3};\n"
                        : "+f"(acc[mf][nf][0]), "+f"(acc[mf][nf][1]),
                          "+f"(acc[mf][nf][2]), "+f"(acc[mf][nf][3])
                        : "r"(af[mf][0]), "r"(af[mf][1]), "r"(af[mf][2]), "r"(af[mf][3]),
                          "r"(bf[nf][0]), "r"(bf[nf][1]));
        }
        __syncthreads();
    }

    #pragma unroll
    for (int mf = 0; mf < 2; mf++) {
        #pragma unroll
        for (int nf = 0; nf < 4; nf++) {
            int row = bm + wm + mf * 16 + gq;
            int col = bn + wn + nf * 8 + tg * 2;
            #pragma unroll
            for (int q = 0; q < 4; q++) {
                int r = row + (q >> 1) * 8;
                int c = col + (q & 1);
                if (c < N) {
                    float v = acc[mf][nf][q] + (bias ? bias[(size_t)c * bstr] : 0.f);
                    if (act) v = v > 0.f ? v : 0.01f * v;
                    C[(size_t)r * ldc + c] = v;
                }
            }
        }
    }
}

// ------------------------- LSTM recurrence (2 pipelined groups/cluster) -----
// 4 clusters of 8 CTAs; cluster c handles dir = c>>1, batches {2*(c&1), +1}.
// Same Whh for both groups -> weight registers shared. Per step the CTA
// alternates groups; group A's fabric flight is hidden behind group B's
// processing. Per-group protocol = R7 flags (poll volatile + one acquire,
// push 32B/lane from warp 0, st.release flag).
__device__ __forceinline__ float sigm(float x) { return 1.f / (1.f + __expf(-x)); }
__device__ __forceinline__ float ftanh(float x) {
    float e = __expf(2.f * x);
    return 1.f - __fdividef(2.f, e + 1.f);
}
__device__ __forceinline__ void fma2(unsigned long long& acc,
                                     unsigned long long a, unsigned long long b) {
    asm("fma.rn.f32x2 %0, %1, %2, %0;" : "+l"(acc) : "l"(a), "l"(b));
}
__device__ __forceinline__ void add2(unsigned long long& a, unsigned long long b) {
    asm("add.rn.f32x2 %0, %0, %1;" : "+l"(a) : "l"(b));
}
__device__ __forceinline__ float pairsum(unsigned long long p) {
    uint32_t lo, hi;
    asm("mov.b64 {%0,%1}, %2;" : "=r"(lo), "=r"(hi) : "l"(p));
    return __uint_as_float(lo) + __uint_as_float(hi);
}

__global__ void __launch_bounds__(256, 1) __cluster_dims__(CPG, 1, 1)
lstm_kernel(const float* __restrict__ Whh_f, const float* __restrict__ Whh_b)
{
    __shared__ __align__(16) float    hs2[2][2][PSTR];   // [group][parity]
    __shared__ __align__(16) float    red[2][128];
    __shared__ __align__(16) float    hstage[2][2][UPC]; // [group][parity]
    __shared__ __align__(16) uint32_t flags[2][CPG];

    int cid = blockIdx.x / CPG;
    uint32_t cig;
    asm("mov.u32 %0, %%cluster_ctarank;" : "=r"(cig));
    int d     = cid >> 1;
    int bpair = (cid & 1) * 2;
    int tid  = threadIdx.x;
    int w    = tid >> 5;
    int lane = tid & 31;
    int row  = w * 16 + (lane & 15);   // gate row 0..127 within CTA
    int kh   = lane >> 4;              // K half
    int gi   = row >> 5;               // gate 0..3
    int ul   = row & 31;               // unit within CTA
    int j    = (int)cig * UPC + ul;    // global unit
    int grow = gi * HID + j;           // Whh row / G column
    const float* Whh = d ? Whh_b : Whh_f;
    const float* Gd  = &g_G[d][0][0];

    // weights: this thread's K-half of one gate row = 32 ulonglong2 (shared by both groups)
    ulonglong2 w2[32];
    #pragma unroll
    for (int q = 0; q < 32; q++)
        w2[q] = *reinterpret_cast<const ulonglong2*>(
            &Whh[(size_t)grow * HID + kh * 128 + q * 4]);

    for (int i = tid; i < 4 * PSTR; i += 256) ((float*)hs2)[i] = 0.f;
    if (tid < 2 * CPG) ((uint32_t*)flags)[tid] = 0u;
    __syncthreads();
    asm volatile("barrier.cluster.arrive.aligned;" ::: "memory");
    asm volatile("barrier.cluster.wait.aligned;"  ::: "memory");

    uint32_t hs_u32  = (uint32_t)__cvta_generic_to_shared(&hs2[0][0][0]);
    uint32_t flg_u32 = (uint32_t)__cvta_generic_to_shared(&flags[0][0]);

    // push dst base: this CTA's slot in rank (lane>>2)&7's hs2[0][0]; per
    // (group,parity) add (g*2+P)*PSTR*4 (mapa is offset-linear within a rank)
    int ds = (int)cig * UPC + ((int)cig >= 4 ? 4 : 0);
    uint32_t rbase;
    {
        int rnk = (lane >> 2) & 7, seg = lane & 3;
        uint32_t laddr = hs_u32 + (uint32_t)ds * 4u + (uint32_t)seg * 32u;
        asm("mapa.shared::cluster.u32 %0, %1, %2;"
            : "=r"(rbase) : "r"(laddr), "r"(rnk));
    }
    uint32_t fbase;   // remote flags[0][cig] in rank = lane&7
    {
        uint32_t laddr = flg_u32 + cig * 4u;
        asm("mapa.shared::cluster.u32 %0, %1, %2;"
            : "=r"(fbase) : "r"(laddr), "r"(lane & 7));
    }

    float cst[2] = {0.f, 0.f};

    for (int st = 0; st < SEQ; st++) {
        int t = d ? (SEQ - 1 - st) : st;
        int cur = st & 1, nxt = cur ^ 1;

        // prefetch both groups' preactivations before any wait
        float gin[2] = {0.f, 0.f};
        if (kh == 0) {
            #pragma unroll
            for (int g = 0; g < 2; g++)
                gin[g] = __ldg(&Gd[(size_t)((bpair + g) * SEQ + t) * G4 + grow]);
        }

        #pragma unroll
        for (int g = 0; g < 2; g++) {
            // warp 0 polls group g's flags; others park at the barrier
            if (w == 0) {
                uint32_t pa = flg_u32 + (uint32_t)(g * CPG + (lane & 7)) * 4u;
                uint32_t tgt = (uint32_t)st;
                while (true) {
                    uint32_t f = 0xffffffffu;
                    if (lane < 8)
                        asm volatile("ld.volatile.shared.u32 %0, [%1];"
                                     : "=r"(f) : "r"(pa));
                    if (__all_sync(0xffffffffu, f >= tgt)) break;
                }
                if (lane < 8) {
                    uint32_t f2;
                    asm volatile("ld.acquire.cluster.shared::cta.u32 %0, [%1];"
                                 : "=r"(f2) : "r"(pa));
                }
            }
            __syncthreads();

            // deferred global store of step st-1's h for this group
            if (w == 1 + g && st > 0) {
                int tp = d ? (SEQ - st) : (st - 1);
                g_hcat[(bpair + g) * SEQ + tp][d * HID + (int)cig * UPC + lane]
                    = hstage[g][(st - 1) & 1][lane];
            }

            // matvec: one gate row, this K-half (64 fma2)
            const float* hb = &hs2[g][cur][kh * HPAD];
            unsigned long long acc[4] = {0ull, 0ull, 0ull, 0ull};
            #pragma unroll
            for (int q = 0; q < 32; q++) {
                const ulonglong2 hv = *reinterpret_cast<const ulonglong2*>(hb + q * 4);
                fma2(acc[q & 3], w2[q].x, hv.x);
                fma2(acc[q & 3], w2[q].y, hv.y);
            }
            add2(acc[0], acc[2]); add2(acc[1], acc[3]); add2(acc[0], acc[1]);
            float s = pairsum(acc[0]);
            s += __shfl_xor_sync(0xffffffffu, s, 16);
            if (kh == 0) {
                float pre = s + gin[g];
                red[g][row] = (gi == 2) ? ftanh(pre) : sigm(pre);
            }
            __syncthreads();

            if (w == 0) {
                float iv = red[g][lane],      fv = red[g][32 + lane];
                float gv = red[g][64 + lane], ov = red[g][96 + lane];
                cst[g] = fv * cst[g] + iv * gv;
                float h = ov * ftanh(cst[g]);
                hstage[g][cur][lane] = h;
                __syncwarp();
                if (st < SEQ - 1) {
                    int seg = lane & 3;
                    const ulonglong2* sp =
                        reinterpret_cast<const ulonglong2*>(&hstage[g][cur][0]) + seg * 2;
                    ulonglong2 v0 = sp[0], v1 = sp[1];
                    uint32_t dst = rbase + (uint32_t)((g * 2 + nxt) * PSTR) * 4u;
                    asm volatile("st.shared::cluster.b64 [%0], %1;" :: "r"(dst      ), "l"(v0.x) : "memory");
                    asm volatile("st.shared::cluster.b64 [%0], %1;" :: "r"(dst +  8u), "l"(v0.y) : "memory");
                    asm volatile("st.shared::cluster.b64 [%0], %1;" :: "r"(dst + 16u), "l"(v1.x) : "memory");
                    asm volatile("st.shared::cluster.b64 [%0], %1;" :: "r"(dst + 24u), "l"(v1.y) : "memory");
                    __syncwarp();
                    if (lane < 8)
                        asm volatile("st.release.cluster.shared::cluster.u32 [%0], %1;"
                                     :: "r"(fbase + (uint32_t)(g * CPG) * 4u),
                                        "r"((uint32_t)(st + 1)) : "memory");
                }
            }
        }
    }

    // flush the final step's h for both groups
    __syncthreads();
    if (w == 1 || w == 2) {
        int g = w - 1;
        int tp = d ? 0 : (SEQ - 1);
        g_hcat[(bpair + g) * SEQ + tp][d * HID + (int)cig * UPC + lane]
            = hstage[g][(SEQ - 1) & 1][lane];
    }

    asm volatile("barrier.cluster.arrive.aligned;" ::: "memory");
    asm volatile("barrier.cluster.wait.aligned;"  ::: "memory");
}

// ------------------------- final assembly -----------------------------------
// out[b][k][m][n] = s_head[b,k,m] + s_tail[b,k,n] + sztab[k][clamp(n-m)]
__global__ void __launch_bounds__(256) assemble_kernel(float* __restrict__ out)
{
    int b = blockIdx.z, k = blockIdx.y, m0 = blockIdx.x * 16;
    int tid = threadIdx.x;
    __shared__ float st_s[SEQ];
    __shared__ float sz_s[NPOS];
    __shared__ float sh_s[16];
    for (int i = tid; i < SEQ; i += 256) st_s[i] = g_stail[b * SEQ + i][k];
    if (tid < NPOS) sz_s[tid] = g_sztab[k][tid];
    if (tid < 16)   sh_s[tid] = g_shead[b * SEQ + m0 + tid][k];
    __syncthreads();

    float* orow = out + (((size_t)(b * NOUT + k)) * SEQ + m0) * SEQ;
    #pragma unroll
    for (int it = 0; it < 8; it++) {
        int lin = it * 256 + tid;
        int r = lin >> 7;
        int n4 = (lin & 127) << 2;
        int m = m0 + r;
        float sh = sh_s[r];
        float4 v;
        int e;
        e = min(max(n4     - m, -15), 14) + 15; v.x = sh + st_s[n4    ] + sz_s[e];
        e = min(max(n4 + 1 - m, -15), 14) + 15; v.y = sh + st_s[n4 + 1] + sz_s[e];
        e = min(max(n4 + 2 - m, -15), 14) + 15; v.z = sh + st_s[n4 + 2] + sz_s[e];
        e = min(max(n4 + 3 - m, -15), 14) + 15; v.w = sh + st_s[n4 + 3] + sz_s[e];
        *reinterpret_cast<float4*>(orow + (size_t)r * SEQ + n4) = v;
    }
}

// ------------------------- launch -------------------------------------------
extern "C" void kernel_launch(void* const* d_in, const int* in_sizes, int n_in,
                              void* d_out, int out_size)
{
    const float* x      = (const float*)d_in[0];
    const float* Wih_f  = (const float*)d_in[1];
    const float* Whh_f  = (const float*)d_in[2];
    const float* bih_f  = (const float*)d_in[3];
    const float* bhh_f  = (const float*)d_in[4];
    const float* Wih_b  = (const float*)d_in[5];
    const float* Whh_b  = (const float*)d_in[6];
    const float* bih_b  = (const float*)d_in[7];
    const float* bhh_b  = (const float*)d_in[8];
    const float* W_head = (const float*)d_in[9];
    const float* b_head = (const float*)d_in[10];
    const float* W_tail = (const float*)d_in[11];
    const float* b_tail = (const float*)d_in[12];
    const float* emb    = (const float*)d_in[13];
    const float* W      = (const float*)d_in[14];
    float* out = (float*)d_out;

    float *pG, *pBias, *pHcat, *pHead, *pTail, *pShead, *pStail;
    cudaGetSymbolAddress((void**)&pG,     g_G);
    cudaGetSymbolAddress((void**)&pBias,  g_bias);
    cudaGetSymbolAddress((void**)&pHcat,  g_hcat);
    cudaGetSymbolAddress((void**)&pHead,  g_head);
    cudaGetSymbolAddress((void**)&pTail,  g_tail);
    cudaGetSymbolAddress((void**)&pShead, g_shead);
    cudaGetSymbolAddress((void**)&pStail, g_stail);

    prep_kernel<<<8, 256>>>(bih_f, bhh_f, bih_b, bhh_b, emb, W);

    // Stage 1: gate input projections (both directions)
    gemm_tf32<<<dim3(G4 / 64, ROWS / 64), 128>>>(x, D_IN, Wih_f, D_IN,
        pBias, 1, pG, G4, G4, D_IN, 0);
    gemm_tf32<<<dim3(G4 / 64, ROWS / 64), 128>>>(x, D_IN, Wih_b, D_IN,
        pBias + G4, 1, pG + (size_t)ROWS * G4, G4, G4, D_IN, 0);

    // Stage 2: recurrence (4 clusters x 2 pipelined groups)
    lstm_kernel<<<NCLUS * CPG, 256>>>(Whh_f, Whh_b);

    // Stage 3: head / tail projections with leaky_relu
    gemm_tf32<<<dim3(MID / 64, ROWS / 64), 128>>>(pHcat, MID, W_head, MID,
        b_head, 1, pHead, MID, MID, MID, 1);
    gemm_tf32<<<dim3(MID / 64, ROWS / 64), 128>>>(pHcat, MID, W_tail, MID,
        b_tail, 1, pTail, MID, MID, MID, 1);

    // Stage 4: biaffine projections (k=50), bias = "ones" column of W
    gemm_tf32<<<dim3(1, ROWS / 64), 128>>>(pHead, MID, W, WLD,
        W + MID, WLD, pShead, NOUT, NOUT, MID, 0);
    gemm_tf32<<<dim3(1, ROWS / 64), 128>>>(pTail, MID, W + (MID + 1), WLD,
        W + (MID + 1) + MID, WLD, pStail, NOUT, NOUT, MID, 0);

    // Stage 5: assemble 210MB output
    assemble_kernel<<<dim3(SEQ / 16, NOUT, NB), 256>>>(out);
}

// round 13
// speedup vs baseline: 1.6033x; 1.6033x over previous
#include <cuda_runtime.h>
#include <cstdint>

#define D_IN 1024
#define HID  256
#define G4   1024
#define MID  512
#define SEQ  512
#define NB   4
#define NOUT 50
#define SED  64
#define NPOS 30
#define WLD  1090           // 2*(MID+1) + SED
#define ROWS 2048           // NB*SEQ
#define CPG  8              // CTAs per recurrence group (== cluster size)
#define UPC  32             // hidden units per CTA
#define NGRP 8              // 2 dirs * 4 batch
#define HPAD 132            // floats per K-half (128 + 4 pad)
#define PSTR (2 * HPAD)     // floats per parity buffer

// ------------------------- scratch (static device memory) -------------------
__device__ float g_G[2][ROWS][G4];      // gate input preactivations (+bias)
__device__ float g_bias[2][G4];
__device__ float g_hcat[ROWS][MID];     // [b*SEQ+t][dir*HID + j]
__device__ float g_head[ROWS][MID];
__device__ float g_tail[ROWS][MID];
__device__ float g_shead[ROWS][NOUT];   // [(b,m)][k]
__device__ float g_stail[ROWS][NOUT];   // [(b,n)][k]
__device__ float g_sztab[NOUT][NPOS];

// ------------------------- prep: bias, size table ---------------------------
__global__ void prep_kernel(const float* __restrict__ bih_f, const float* __restrict__ bhh_f,
                            const float* __restrict__ bih_b, const float* __restrict__ bhh_b,
                            const float* __restrict__ emb,   const float* __restrict__ W)
{
    int g = blockIdx.x * blockDim.x + threadIdx.x;
    if (g < G4)            g_bias[0][g]      = bih_f[g]      + bhh_f[g];
    else if (g < 2 * G4)   g_bias[1][g - G4] = bih_b[g - G4] + bhh_b[g - G4];
    if (g < NOUT * NPOS) {
        int k = g / NPOS, p = g % NPOS;
        float s = 0.f;
        #pragma unroll 8
        for (int h = 0; h < SED; h++)
            s += emb[p * SED + h] * W[k * WLD + 2 * (MID + 1) + h];
        g_sztab[k][p] = s;
    }
}

// ------------------------- tf32 GEMM: C = A @ B^T (+bias, opt leaky) --------
__device__ __forceinline__ float to_tf32(float x) {
    uint32_t u;
    asm("cvt.rna.tf32.f32 %0, %1;" : "=r"(u) : "f"(x));
    return __uint_as_float(u);
}

__global__ void __launch_bounds__(128) gemm_tf32(
    const float* __restrict__ A, int lda,
    const float* __restrict__ Bw, int ldb,
    const float* __restrict__ bias, int bstr,
    float* __restrict__ C, int ldc,
    int N, int K, int act)
{
    __shared__ float As[64][33];
    __shared__ float Bs[64][33];
    int tid  = threadIdx.x;
    int warp = tid >> 5, lane = tid & 31;
    int gq = lane >> 2, tg = lane & 3;
    int wm = (warp >> 1) * 32, wn = (warp & 1) * 32;
    int bm = blockIdx.y * 64, bn = blockIdx.x * 64;

    float acc[2][4][4];
    #pragma unroll
    for (int a = 0; a < 2; a++)
        #pragma unroll
        for (int b = 0; b < 4; b++)
            #pragma unroll
            for (int c = 0; c < 4; c++) acc[a][b][c] = 0.f;

    bool bvec = ((ldb & 3) == 0);

    for (int k0 = 0; k0 < K; k0 += 32) {
        #pragma unroll
        for (int i = 0; i < 4; i++) {
            int l4 = tid + i * 128;
            int r = l4 >> 3, c4 = (l4 & 7) << 2;
            const float4 v = *reinterpret_cast<const float4*>(A + (size_t)(bm + r) * lda + k0 + c4);
            As[r][c4 + 0] = to_tf32(v.x); As[r][c4 + 1] = to_tf32(v.y);
            As[r][c4 + 2] = to_tf32(v.z); As[r][c4 + 3] = to_tf32(v.w);
        }
        #pragma unroll
        for (int i = 0; i < 4; i++) {
            int l4 = tid + i * 128;
            int r = l4 >> 3, c4 = (l4 & 7) << 2;
            float4 v;
            if (bn + r < N) {
                if (bvec) {
                    v = *reinterpret_cast<const float4*>(Bw + (size_t)(bn + r) * ldb + k0 + c4);
                } else {
                    const float* p = Bw + (size_t)(bn + r) * ldb + k0 + c4;
                    v = make_float4(p[0], p[1], p[2], p[3]);
                }
            } else v = make_float4(0.f, 0.f, 0.f, 0.f);
            Bs[r][c4 + 0] = to_tf32(v.x); Bs[r][c4 + 1] = to_tf32(v.y);
            Bs[r][c4 + 2] = to_tf32(v.z); Bs[r][c4 + 3] = to_tf32(v.w);
        }
        __syncthreads();

        #pragma unroll
        for (int kk = 0; kk < 32; kk += 8) {
            uint32_t af[2][4], bf[4][2];
            #pragma unroll
            for (int mf = 0; mf < 2; mf++) {
                int r0 = wm + mf * 16 + gq;
                af[mf][0] = __float_as_uint(As[r0    ][kk + tg]);
                af[mf][1] = __float_as_uint(As[r0 + 8][kk + tg]);
                af[mf][2] = __float_as_uint(As[r0    ][kk + tg + 4]);
                af[mf][3] = __float_as_uint(As[r0 + 8][kk + tg + 4]);
            }
            #pragma unroll
            for (int nf = 0; nf < 4; nf++) {
                int n0 = wn + nf * 8 + gq;
                bf[nf][0] = __float_as_uint(Bs[n0][kk + tg]);
                bf[nf][1] = __float_as_uint(Bs[n0][kk + tg + 4]);
            }
            #pragma unroll
            for (int mf = 0; mf < 2; mf++)
                #pragma unroll
                for (int nf = 0; nf < 4; nf++)
                    asm volatile(
                        "mma.sync.aligned.m16n8k8.row.col.f32.tf32.tf32.f32 "
                        "{%0,%1,%2,%3}, {%4,%5,%6,%7}, {%8,%9}, {%0,%1,%2,%3};\n"
                        : "+f"(acc[mf][nf][0]), "+f"(acc[mf][nf][1]),
                          "+f"(acc[mf][nf][2]), "+f"(acc[mf][nf][3])
                        : "r"(af[mf][0]), "r"(af[mf][1]), "r"(af[mf][2]), "r"(af[mf][3]),
                          "r"(bf[nf][0]), "r"(bf[nf][1]));
        }
        __syncthreads();
    }

    #pragma unroll
    for (int mf = 0; mf < 2; mf++) {
        #pragma unroll
        for (int nf = 0; nf < 4; nf++) {
            int row = bm + wm + mf * 16 + gq;
            int col = bn + wn + nf * 8 + tg * 2;
            #pragma unroll
            for (int q = 0; q < 4; q++) {
                int r = row + (q >> 1) * 8;
                int c = col + (q & 1);
                if (c < N) {
                    float v = acc[mf][nf][q] + (bias ? bias[(size_t)c * bstr] : 0.f);
                    if (act) v = v > 0.f ? v : 0.01f * v;
                    C[(size_t)r * ldc + c] = v;
                }
            }
        }
    }
}

// ------------------------- LSTM recurrence ----------------------------------
// R7 layout (256 thr = 128 gate rows x 2 K-halves, 8-CTA cluster, flags sync)
// with DECOUPLED epilogue: workers bar.arrive (non-blocking) and immediately
// proceed to poll step st+1; only warp 0 bar.syncs, combines gates, pushes h,
// and releases flags. Warp 0's epilogue + fabric flight overlap the workers'
// poll/prefetch instead of blocking them. red[] double-buffered by parity.
__device__ __forceinline__ float sigm(float x) { return 1.f / (1.f + __expf(-x)); }
__device__ __forceinline__ float ftanh(float x) {
    float e = __expf(2.f * x);
    return 1.f - __fdividef(2.f, e + 1.f);
}
__device__ __forceinline__ void fma2(unsigned long long& acc,
                                     unsigned long long a, unsigned long long b) {
    asm("fma.rn.f32x2 %0, %1, %2, %0;" : "+l"(acc) : "l"(a), "l"(b));
}
__device__ __forceinline__ void add2(unsigned long long& a, unsigned long long b) {
    asm("add.rn.f32x2 %0, %0, %1;" : "+l"(a) : "l"(b));
}
__device__ __forceinline__ float pairsum(unsigned long long p) {
    uint32_t lo, hi;
    asm("mov.b64 {%0,%1}, %2;" : "=r"(lo), "=r"(hi) : "l"(p));
    return __uint_as_float(lo) + __uint_as_float(hi);
}

__global__ void __launch_bounds__(256, 1) __cluster_dims__(CPG, 1, 1)
lstm_kernel(const float* __restrict__ Whh_f, const float* __restrict__ Whh_b)
{
    __shared__ __align__(16) float    hs2[2][PSTR];
    __shared__ __align__(16) float    red[2][128];
    __shared__ __align__(16) float    hstage[2][UPC];
    __shared__ __align__(16) uint32_t flags[CPG];

    int grp = blockIdx.x / CPG;
    uint32_t cig;
    asm("mov.u32 %0, %%cluster_ctarank;" : "=r"(cig));
    int d = grp >> 2, b = grp & 3;
    int tid  = threadIdx.x;
    int w    = tid >> 5;
    int lane = tid & 31;
    int row  = w * 16 + (lane & 15);   // gate row 0..127 within CTA
    int kh   = lane >> 4;              // K half
    int gi   = row >> 5;               // gate 0..3
    int ul   = row & 31;               // unit within CTA
    int j    = (int)cig * UPC + ul;    // global unit
    int grow = gi * HID + j;           // Whh row / G column
    const float* Whh = d ? Whh_b : Whh_f;
    const float* Gd  = &g_G[d][0][0];

    // weights: this thread's K-half of one gate row = 32 ulonglong2
    ulonglong2 w2[32];
    #pragma unroll
    for (int q = 0; q < 32; q++)
        w2[q] = *reinterpret_cast<const ulonglong2*>(
            &Whh[(size_t)grow * HID + kh * 128 + q * 4]);

    for (int i = tid; i < 2 * PSTR; i += 256) ((float*)hs2)[i] = 0.f;
    if (tid < CPG) flags[tid] = 0u;
    __syncthreads();
    asm volatile("barrier.cluster.arrive.aligned;" ::: "memory");
    asm volatile("barrier.cluster.wait.aligned;"  ::: "memory");

    uint32_t hs_u32  = (uint32_t)__cvta_generic_to_shared(&hs2[0][0]);
    uint32_t flg_u32 = (uint32_t)__cvta_generic_to_shared(&flags[0]);
    uint32_t my_flag_addr = flg_u32 + (uint32_t)(lane & 7) * 4u;

    // push dst: this CTA's 32-float slot in each rank's hs2, split 4x32B
    int ds = (int)cig * UPC + ((int)cig >= 4 ? 4 : 0);
    uint32_t ra[2];
    {
        int rnk = (lane >> 2) & 7, seg = lane & 3;
        #pragma unroll
        for (int P = 0; P < 2; P++) {
            uint32_t laddr = hs_u32 + (uint32_t)(P * PSTR + ds) * 4u + (uint32_t)seg * 32u;
            asm("mapa.shared::cluster.u32 %0, %1, %2;"
                : "=r"(ra[P]) : "r"(laddr), "r"(rnk));
        }
    }
    uint32_t fa;
    {
        uint32_t laddr = flg_u32 + cig * 4u;
        asm("mapa.shared::cluster.u32 %0, %1, %2;"
            : "=r"(fa) : "r"(laddr), "r"(lane & 7));
    }

    float cst = 0.f;

    for (int st = 0; st < SEQ; st++) {
        int t = d ? (SEQ - 1 - st) : st;
        int cur = st & 1, nxt = cur ^ 1;

        // prefetch this row's preactivation before the wait
        float gin = 0.f;
        if (kh == 0)
            gin = __ldg(&Gd[(size_t)(b * SEQ + t) * G4 + grow]);

        // EVERY warp polls independently (workers arrive here early, while
        // warp 0 of this CTA is still in its previous-step epilogue)
        {
            uint32_t tgt = (uint32_t)st;
            while (true) {
                uint32_t f = 0xffffffffu;
                if (lane < 8)
                    asm volatile("ld.volatile.shared.u32 %0, [%1];"
                                 : "=r"(f) : "r"(my_flag_addr));
                if (__all_sync(0xffffffffu, f >= tgt)) break;
            }
            if (lane < 8) {
                uint32_t f2;
                asm volatile("ld.acquire.cluster.shared::cta.u32 %0, [%1];"
                             : "=r"(f2) : "r"(my_flag_addr));
            }
        }

        // warp 1: deferred global store of step st-1's h (visible via acquire)
        if (w == 1 && st > 0) {
            int tp = d ? (SEQ - st) : (st - 1);
            g_hcat[b * SEQ + tp][d * HID + (int)cig * UPC + lane] = hstage[(st - 1) & 1][lane];
        }

        // matvec: one gate row, this K-half (64 fma2)
        const float* hb = &hs2[cur][kh * HPAD];
        unsigned long long acc[4] = {0ull, 0ull, 0ull, 0ull};
        #pragma unroll
        for (int q = 0; q < 32; q++) {
            const ulonglong2 hv = *reinterpret_cast<const ulonglong2*>(hb + q * 4);
            fma2(acc[q & 3], w2[q].x, hv.x);
            fma2(acc[q & 3], w2[q].y, hv.y);
        }
        add2(acc[0], acc[2]); add2(acc[1], acc[3]); add2(acc[0], acc[1]);
        float s = pairsum(acc[0]);
        s += __shfl_xor_sync(0xffffffffu, s, 16);
        if (kh == 0) {
            float pre = s + gin;
            red[cur][row] = (gi == 2) ? ftanh(pre) : sigm(pre);
        }

        if (w != 0) {
            // non-blocking arrival; proceed straight to next step's poll
            asm volatile("bar.arrive 1, 256;" ::: "memory");
        } else {
            asm volatile("bar.sync 1, 256;" ::: "memory");
            float iv = red[cur][lane],      fv = red[cur][32 + lane];
            float gv = red[cur][64 + lane], ov = red[cur][96 + lane];
            cst = fv * cst + iv * gv;
            float h = ov * ftanh(cst);
            hstage[cur][lane] = h;
            __syncwarp();
            if (st < SEQ - 1) {
                int seg = lane & 3;
                const ulonglong2* sp = reinterpret_cast<const ulonglong2*>(&hstage[cur][0]) + seg * 2;
                ulonglong2 v0 = sp[0], v1 = sp[1];
                uint32_t dst = ra[nxt];
                asm volatile("st.shared::cluster.b64 [%0], %1;" :: "r"(dst      ), "l"(v0.x) : "memory");
                asm volatile("st.shared::cluster.b64 [%0], %1;" :: "r"(dst +  8u), "l"(v0.y) : "memory");
                asm volatile("st.shared::cluster.b64 [%0], %1;" :: "r"(dst + 16u), "l"(v1.x) : "memory");
                asm volatile("st.shared::cluster.b64 [%0], %1;" :: "r"(dst + 24u), "l"(v1.y) : "memory");
                __syncwarp();
                if (lane < 8)
                    asm volatile("st.release.cluster.shared::cluster.u32 [%0], %1;"
                                 :: "r"(fa), "r"((uint32_t)(st + 1)) : "memory");
            }
        }
    }

    // flush the final step's h
    __syncthreads();
    if (w == 1) {
        int tp = d ? 0 : (SEQ - 1);
        g_hcat[b * SEQ + tp][d * HID + (int)cig * UPC + lane] = hstage[(SEQ - 1) & 1][lane];
    }

    asm volatile("barrier.cluster.arrive.aligned;" ::: "memory");
    asm volatile("barrier.cluster.wait.aligned;"  ::: "memory");
}

// ------------------------- final assembly -----------------------------------
// out[b][k][m][n] = s_head[b,k,m] + s_tail[b,k,n] + sztab[k][clamp(n-m)]
__global__ void __launch_bounds__(256) assemble_kernel(float* __restrict__ out)
{
    int b = blockIdx.z, k = blockIdx.y, m0 = blockIdx.x * 16;
    int tid = threadIdx.x;
    __shared__ float st_s[SEQ];
    __shared__ float sz_s[NPOS];
    __shared__ float sh_s[16];
    for (int i = tid; i < SEQ; i += 256) st_s[i] = g_stail[b * SEQ + i][k];
    if (tid < NPOS) sz_s[tid] = g_sztab[k][tid];
    if (tid < 16)   sh_s[tid] = g_shead[b * SEQ + m0 + tid][k];
    __syncthreads();

    float* orow = out + (((size_t)(b * NOUT + k)) * SEQ + m0) * SEQ;
    #pragma unroll
    for (int it = 0; it < 8; it++) {
        int lin = it * 256 + tid;
        int r = lin >> 7;
        int n4 = (lin & 127) << 2;
        int m = m0 + r;
        float sh = sh_s[r];
        float4 v;
        int e;
        e = min(max(n4     - m, -15), 14) + 15; v.x = sh + st_s[n4    ] + sz_s[e];
        e = min(max(n4 + 1 - m, -15), 14) + 15; v.y = sh + st_s[n4 + 1] + sz_s[e];
        e = min(max(n4 + 2 - m, -15), 14) + 15; v.z = sh + st_s[n4 + 2] + sz_s[e];
        e = min(max(n4 + 3 - m, -15), 14) + 15; v.w = sh + st_s[n4 + 3] + sz_s[e];
        *reinterpret_cast<float4*>(orow + (size_t)r * SEQ + n4) = v;
    }
}

// ------------------------- launch -------------------------------------------
extern "C" void kernel_launch(void* const* d_in, const int* in_sizes, int n_in,
                              void* d_out, int out_size)
{
    const float* x      = (const float*)d_in[0];
    const float* Wih_f  = (const float*)d_in[1];
    const float* Whh_f  = (const float*)d_in[2];
    const float* bih_f  = (const float*)d_in[3];
    const float* bhh_f  = (const float*)d_in[4];
    const float* Wih_b  = (const float*)d_in[5];
    const float* Whh_b  = (const float*)d_in[6];
    const float* bih_b  = (const float*)d_in[7];
    const float* bhh_b  = (const float*)d_in[8];
    const float* W_head = (const float*)d_in[9];
    const float* b_head = (const float*)d_in[10];
    const float* W_tail = (const float*)d_in[11];
    const float* b_tail = (const float*)d_in[12];
    const float* emb    = (const float*)d_in[13];
    const float* W      = (const float*)d_in[14];
    float* out = (float*)d_out;

    float *pG, *pBias, *pHcat, *pHead, *pTail, *pShead, *pStail;
    cudaGetSymbolAddress((void**)&pG,     g_G);
    cudaGetSymbolAddress((void**)&pBias,  g_bias);
    cudaGetSymbolAddress((void**)&pHcat,  g_hcat);
    cudaGetSymbolAddress((void**)&pHead,  g_head);
    cudaGetSymbolAddress((void**)&pTail,  g_tail);
    cudaGetSymbolAddress((void**)&pShead, g_shead);
    cudaGetSymbolAddress((void**)&pStail, g_stail);

    prep_kernel<<<8, 256>>>(bih_f, bhh_f, bih_b, bhh_b, emb, W);

    // Stage 1: gate input projections (both directions)
    gemm_tf32<<<dim3(G4 / 64, ROWS / 64), 128>>>(x, D_IN, Wih_f, D_IN,
        pBias, 1, pG, G4, G4, D_IN, 0);
    gemm_tf32<<<dim3(G4 / 64, ROWS / 64), 128>>>(x, D_IN, Wih_b, D_IN,
        pBias + G4, 1, pG + (size_t)ROWS * G4, G4, G4, D_IN, 0);

    // Stage 2: recurrence (both directions, all batches in parallel)
    lstm_kernel<<<NGRP * CPG, 256>>>(Whh_f, Whh_b);

    // Stage 3: head / tail projections with leaky_relu
    gemm_tf32<<<dim3(MID / 64, ROWS / 64), 128>>>(pHcat, MID, W_head, MID,
        b_head, 1, pHead, MID, MID, MID, 1);
    gemm_tf32<<<dim3(MID / 64, ROWS / 64), 128>>>(pHcat, MID, W_tail, MID,
        b_tail, 1, pTail, MID, MID, MID, 1);

    // Stage 4: biaffine projections (k=50), bias = "ones" column of W
    gemm_tf32<<<dim3(1, ROWS / 64), 128>>>(pHead, MID, W, WLD,
        W + MID, WLD, pShead, NOUT, NOUT, MID, 0);
    gemm_tf32<<<dim3(1, ROWS / 64), 128>>>(pTail, MID, W + (MID + 1), WLD,
        W + (MID + 1) + MID, WLD, pStail, NOUT, NOUT, MID, 0);

    // Stage 5: assemble 210MB output
    assemble_kernel<<<dim3(SEQ / 16, NOUT, NB), 256>>>(out);
}

// round 14
// speedup vs baseline: 1.7282x; 1.0779x over previous
#include <cuda_runtime.h>
#include <cstdint>

#define D_IN 1024
#define HID  256
#define G4   1024
#define MID  512
#define SEQ  512
#define NB   4
#define NOUT 50
#define SED  64
#define NPOS 30
#define WLD  1090           // 2*(MID+1) + SED
#define ROWS 2048           // NB*SEQ
#define CPG  8              // CTAs per recurrence group (== cluster size)
#define UPC  32             // hidden units per CTA
#define NGRP 8              // 2 dirs * 4 batch
#define HPAD 132            // floats per K-half (128 + 4 pad)
#define PSTR (2 * HPAD)     // floats per parity buffer

// ------------------------- scratch (static device memory) -------------------
__device__ float g_G[2][ROWS][G4];      // gate input preactivations (+bias)
__device__ float g_bias[2][G4];
__device__ float g_hcat[ROWS][MID];     // [b*SEQ+t][dir*HID + j]
__device__ float g_head[ROWS][MID];
__device__ float g_tail[ROWS][MID];
__device__ float g_shead[ROWS][NOUT];   // [(b,m)][k]
__device__ float g_stail[ROWS][NOUT];   // [(b,n)][k]
__device__ float g_sztab[NOUT][NPOS];

// ------------------------- prep: bias, size table ---------------------------
__global__ void prep_kernel(const float* __restrict__ bih_f, const float* __restrict__ bhh_f,
                            const float* __restrict__ bih_b, const float* __restrict__ bhh_b,
                            const float* __restrict__ emb,   const float* __restrict__ W)
{
    int g = blockIdx.x * blockDim.x + threadIdx.x;
    if (g < G4)            g_bias[0][g]      = bih_f[g]      + bhh_f[g];
    else if (g < 2 * G4)   g_bias[1][g - G4] = bih_b[g - G4] + bhh_b[g - G4];
    if (g < NOUT * NPOS) {
        int k = g / NPOS, p = g % NPOS;
        float s = 0.f;
        #pragma unroll 8
        for (int h = 0; h < SED; h++)
            s += emb[p * SED + h] * W[k * WLD + 2 * (MID + 1) + h];
        g_sztab[k][p] = s;
    }
}

__device__ __forceinline__ float to_tf32(float x) {
    uint32_t u;
    asm("cvt.rna.tf32.f32 %0, %1;" : "=r"(u) : "f"(x));
    return __uint_as_float(u);
}

// ------------------------- big tf32 GEMM: 128x128 tiles, z-batched ----------
// C_z = A @ B_z^T (+bias_z, opt leaky). N, K multiples of 128/32. 256 thr.
__global__ void __launch_bounds__(256) gemm_big(
    const float* __restrict__ A, int lda,
    const float* __restrict__ B0, const float* __restrict__ B1, int ldb,
    const float* __restrict__ bias0, const float* __restrict__ bias1,
    float* __restrict__ C0, float* __restrict__ C1, size_t cstride, int ldc,
    int K, int act)
{
    __shared__ float As[128][33];
    __shared__ float Bs[128][33];
    int z = blockIdx.z;
    const float* Bw   = z ? B1 : B0;
    const float* bias = z ? bias1 : bias0;
    float* C = (z ? C1 : C0);

    int tid  = threadIdx.x;
    int warp = tid >> 5, lane = tid & 31;
    int gq = lane >> 2, tg = lane & 3;
    int wm = (warp >> 1) * 32, wn = (warp & 1) * 64;
    int bm = blockIdx.y * 128, bn = blockIdx.x * 128;

    float acc[2][8][4];
    #pragma unroll
    for (int a = 0; a < 2; a++)
        #pragma unroll
        for (int b = 0; b < 8; b++)
            #pragma unroll
            for (int c = 0; c < 4; c++) acc[a][b][c] = 0.f;

    for (int k0 = 0; k0 < K; k0 += 32) {
        #pragma unroll
        for (int i = 0; i < 4; i++) {
            int l4 = tid + i * 256;
            int r = l4 >> 3, c4 = (l4 & 7) << 2;
            const float4 va = *reinterpret_cast<const float4*>(A + (size_t)(bm + r) * lda + k0 + c4);
            As[r][c4 + 0] = to_tf32(va.x); As[r][c4 + 1] = to_tf32(va.y);
            As[r][c4 + 2] = to_tf32(va.z); As[r][c4 + 3] = to_tf32(va.w);
            const float4 vb = *reinterpret_cast<const float4*>(Bw + (size_t)(bn + r) * ldb + k0 + c4);
            Bs[r][c4 + 0] = to_tf32(vb.x); Bs[r][c4 + 1] = to_tf32(vb.y);
            Bs[r][c4 + 2] = to_tf32(vb.z); Bs[r][c4 + 3] = to_tf32(vb.w);
        }
        __syncthreads();

        #pragma unroll
        for (int kk = 0; kk < 32; kk += 8) {
            uint32_t af[2][4], bf[8][2];
            #pragma unroll
            for (int mf = 0; mf < 2; mf++) {
                int r0 = wm + mf * 16 + gq;
                af[mf][0] = __float_as_uint(As[r0    ][kk + tg]);
                af[mf][1] = __float_as_uint(As[r0 + 8][kk + tg]);
                af[mf][2] = __float_as_uint(As[r0    ][kk + tg + 4]);
                af[mf][3] = __float_as_uint(As[r0 + 8][kk + tg + 4]);
            }
            #pragma unroll
            for (int nf = 0; nf < 8; nf++) {
                int n0 = wn + nf * 8 + gq;
                bf[nf][0] = __float_as_uint(Bs[n0][kk + tg]);
                bf[nf][1] = __float_as_uint(Bs[n0][kk + tg + 4]);
            }
            #pragma unroll
            for (int mf = 0; mf < 2; mf++)
                #pragma unroll
                for (int nf = 0; nf < 8; nf++)
                    asm volatile(
                        "mma.sync.aligned.m16n8k8.row.col.f32.tf32.tf32.f32 "
                        "{%0,%1,%2,%3}, {%4,%5,%6,%7}, {%8,%9}, {%0,%1,%2,%3};\n"
                        : "+f"(acc[mf][nf][0]), "+f"(acc[mf][nf][1]),
                          "+f"(acc[mf][nf][2]), "+f"(acc[mf][nf][3])
                        : "r"(af[mf][0]), "r"(af[mf][1]), "r"(af[mf][2]), "r"(af[mf][3]),
                          "r"(bf[nf][0]), "r"(bf[nf][1]));
        }
        __syncthreads();
    }

    #pragma unroll
    for (int mf = 0; mf < 2; mf++) {
        #pragma unroll
        for (int nf = 0; nf < 8; nf++) {
            int row = bm + wm + mf * 16 + gq;
            int col = bn + wn + nf * 8 + tg * 2;
            #pragma unroll
            for (int q = 0; q < 4; q++) {
                int r = row + (q >> 1) * 8;
                int c = col + (q & 1);
                float v = acc[mf][nf][q] + bias[c];
                if (act) v = v > 0.f ? v : 0.01f * v;
                C[(size_t)r * ldc + c] = v;
            }
        }
    }
}

// ------------------------- small tf32 GEMM (stage 4, N=50) ------------------
__global__ void __launch_bounds__(128) gemm_tf32(
    const float* __restrict__ A, int lda,
    const float* __restrict__ Bw, int ldb,
    const float* __restrict__ bias, int bstr,
    float* __restrict__ C, int ldc,
    int N, int K, int act)
{
    __shared__ float As[64][33];
    __shared__ float Bs[64][33];
    int tid  = threadIdx.x;
    int warp = tid >> 5, lane = tid & 31;
    int gq = lane >> 2, tg = lane & 3;
    int wm = (warp >> 1) * 32, wn = (warp & 1) * 32;
    int bm = blockIdx.y * 64, bn = blockIdx.x * 64;

    float acc[2][4][4];
    #pragma unroll
    for (int a = 0; a < 2; a++)
        #pragma unroll
        for (int b = 0; b < 4; b++)
            #pragma unroll
            for (int c = 0; c < 4; c++) acc[a][b][c] = 0.f;

    bool bvec = ((ldb & 3) == 0);

    for (int k0 = 0; k0 < K; k0 += 32) {
        #pragma unroll
        for (int i = 0; i < 4; i++) {
            int l4 = tid + i * 128;
            int r = l4 >> 3, c4 = (l4 & 7) << 2;
            const float4 v = *reinterpret_cast<const float4*>(A + (size_t)(bm + r) * lda + k0 + c4);
            As[r][c4 + 0] = to_tf32(v.x); As[r][c4 + 1] = to_tf32(v.y);
            As[r][c4 + 2] = to_tf32(v.z); As[r][c4 + 3] = to_tf32(v.w);
        }
        #pragma unroll
        for (int i = 0; i < 4; i++) {
            int l4 = tid + i * 128;
            int r = l4 >> 3, c4 = (l4 & 7) << 2;
            float4 v;
            if (bn + r < N) {
                if (bvec) {
                    v = *reinterpret_cast<const float4*>(Bw + (size_t)(bn + r) * ldb + k0 + c4);
                } else {
                    const float* p = Bw + (size_t)(bn + r) * ldb + k0 + c4;
                    v = make_float4(p[0], p[1], p[2], p[3]);
                }
            } else v = make_float4(0.f, 0.f, 0.f, 0.f);
            Bs[r][c4 + 0] = to_tf32(v.x); Bs[r][c4 + 1] = to_tf32(v.y);
            Bs[r][c4 + 2] = to_tf32(v.z); Bs[r][c4 + 3] = to_tf32(v.w);
        }
        __syncthreads();

        #pragma unroll
        for (int kk = 0; kk < 32; kk += 8) {
            uint32_t af[2][4], bf[4][2];
            #pragma unroll
            for (int mf = 0; mf < 2; mf++) {
                int r0 = wm + mf * 16 + gq;
                af[mf][0] = __float_as_uint(As[r0    ][kk + tg]);
                af[mf][1] = __float_as_uint(As[r0 + 8][kk + tg]);
                af[mf][2] = __float_as_uint(As[r0    ][kk + tg + 4]);
                af[mf][3] = __float_as_uint(As[r0 + 8][kk + tg + 4]);
            }
            #pragma unroll
            for (int nf = 0; nf < 4; nf++) {
                int n0 = wn + nf * 8 + gq;
                bf[nf][0] = __float_as_uint(Bs[n0][kk + tg]);
                bf[nf][1] = __float_as_uint(Bs[n0][kk + tg + 4]);
            }
            #pragma unroll
            for (int mf = 0; mf < 2; mf++)
                #pragma unroll
                for (int nf = 0; nf < 4; nf++)
                    asm volatile(
                        "mma.sync.aligned.m16n8k8.row.col.f32.tf32.tf32.f32 "
                        "{%0,%1,%2,%3}, {%4,%5,%6,%7}, {%8,%9}, {%0,%1,%2,%3};\n"
                        : "+f"(acc[mf][nf][0]), "+f"(acc[mf][nf][1]),
                          "+f"(acc[mf][nf][2]), "+f"(acc[mf][nf][3])
                        : "r"(af[mf][0]), "r"(af[mf][1]), "r"(af[mf][2]), "r"(af[mf][3]),
                          "r"(bf[nf][0]), "r"(bf[nf][1]));
        }
        __syncthreads();
    }

    #pragma unroll
    for (int mf = 0; mf < 2; mf++) {
        #pragma unroll
        for (int nf = 0; nf < 4; nf++) {
            int row = bm + wm + mf * 16 + gq;
            int col = bn + wn + nf * 8 + tg * 2;
            #pragma unroll
            for (int q = 0; q < 4; q++) {
                int r = row + (q >> 1) * 8;
                int c = col + (q & 1);
                if (c < N) {
                    float v = acc[mf][nf][q] + (bias ? bias[(size_t)c * bstr] : 0.f);
                    if (act) v = v > 0.f ? v : 0.01f * v;
                    C[(size_t)r * ldc + c] = v;
                }
            }
        }
    }
}

// ------------------------- LSTM recurrence (R13, unchanged) -----------------
__device__ __forceinline__ float sigm(float x) { return 1.f / (1.f + __expf(-x)); }
__device__ __forceinline__ float ftanh(float x) {
    float e = __expf(2.f * x);
    return 1.f - __fdividef(2.f, e + 1.f);
}
__device__ __forceinline__ void fma2(unsigned long long& acc,
                                     unsigned long long a, unsigned long long b) {
    asm("fma.rn.f32x2 %0, %1, %2, %0;" : "+l"(acc) : "l"(a), "l"(b));
}
__device__ __forceinline__ void add2(unsigned long long& a, unsigned long long b) {
    asm("add.rn.f32x2 %0, %0, %1;" : "+l"(a) : "l"(b));
}
__device__ __forceinline__ float pairsum(unsigned long long p) {
    uint32_t lo, hi;
    asm("mov.b64 {%0,%1}, %2;" : "=r"(lo), "=r"(hi) : "l"(p));
    return __uint_as_float(lo) + __uint_as_float(hi);
}

__global__ void __launch_bounds__(256, 1) __cluster_dims__(CPG, 1, 1)
lstm_kernel(const float* __restrict__ Whh_f, const float* __restrict__ Whh_b)
{
    __shared__ __align__(16) float    hs2[2][PSTR];
    __shared__ __align__(16) float    red[2][128];
    __shared__ __align__(16) float    hstage[2][UPC];
    __shared__ __align__(16) uint32_t flags[CPG];

    int grp = blockIdx.x / CPG;
    uint32_t cig;
    asm("mov.u32 %0, %%cluster_ctarank;" : "=r"(cig));
    int d = grp >> 2, b = grp & 3;
    int tid  = threadIdx.x;
    int w    = tid >> 5;
    int lane = tid & 31;
    int row  = w * 16 + (lane & 15);
    int kh   = lane >> 4;
    int gi   = row >> 5;
    int ul   = row & 31;
    int j    = (int)cig * UPC + ul;
    int grow = gi * HID + j;
    const float* Whh = d ? Whh_b : Whh_f;
    const float* Gd  = &g_G[d][0][0];

    ulonglong2 w2[32];
    #pragma unroll
    for (int q = 0; q < 32; q++)
        w2[q] = *reinterpret_cast<const ulonglong2*>(
            &Whh[(size_t)grow * HID + kh * 128 + q * 4]);

    for (int i = tid; i < 2 * PSTR; i += 256) ((float*)hs2)[i] = 0.f;
    if (tid < CPG) flags[tid] = 0u;
    __syncthreads();
    asm volatile("barrier.cluster.arrive.aligned;" ::: "memory");
    asm volatile("barrier.cluster.wait.aligned;"  ::: "memory");

    uint32_t hs_u32  = (uint32_t)__cvta_generic_to_shared(&hs2[0][0]);
    uint32_t flg_u32 = (uint32_t)__cvta_generic_to_shared(&flags[0]);
    uint32_t my_flag_addr = flg_u32 + (uint32_t)(lane & 7) * 4u;

    int ds = (int)cig * UPC + ((int)cig >= 4 ? 4 : 0);
    uint32_t ra[2];
    {
        int rnk = (lane >> 2) & 7, seg = lane & 3;
        #pragma unroll
        for (int P = 0; P < 2; P++) {
            uint32_t laddr = hs_u32 + (uint32_t)(P * PSTR + ds) * 4u + (uint32_t)seg * 32u;
            asm("mapa.shared::cluster.u32 %0, %1, %2;"
                : "=r"(ra[P]) : "r"(laddr), "r"(rnk));
        }
    }
    uint32_t fa;
    {
        uint32_t laddr = flg_u32 + cig * 4u;
        asm("mapa.shared::cluster.u32 %0, %1, %2;"
            : "=r"(fa) : "r"(laddr), "r"(lane & 7));
    }

    float cst = 0.f;

    for (int st = 0; st < SEQ; st++) {
        int t = d ? (SEQ - 1 - st) : st;
        int cur = st & 1, nxt = cur ^ 1;

        float gin = 0.f;
        if (kh == 0)
            gin = __ldg(&Gd[(size_t)(b * SEQ + t) * G4 + grow]);

        {
            uint32_t tgt = (uint32_t)st;
            while (true) {
                uint32_t f = 0xffffffffu;
                if (lane < 8)
                    asm volatile("ld.volatile.shared.u32 %0, [%1];"
                                 : "=r"(f) : "r"(my_flag_addr));
                if (__all_sync(0xffffffffu, f >= tgt)) break;
            }
            if (lane < 8) {
                uint32_t f2;
                asm volatile("ld.acquire.cluster.shared::cta.u32 %0, [%1];"
                             : "=r"(f2) : "r"(my_flag_addr));
            }
        }

        if (w == 1 && st > 0) {
            int tp = d ? (SEQ - st) : (st - 1);
            g_hcat[b * SEQ + tp][d * HID + (int)cig * UPC + lane] = hstage[(st - 1) & 1][lane];
        }

        const float* hb = &hs2[cur][kh * HPAD];
        unsigned long long acc[4] = {0ull, 0ull, 0ull, 0ull};
        #pragma unroll
        for (int q = 0; q < 32; q++) {
            const ulonglong2 hv = *reinterpret_cast<const ulonglong2*>(hb + q * 4);
            fma2(acc[q & 3], w2[q].x, hv.x);
            fma2(acc[q & 3], w2[q].y, hv.y);
        }
        add2(acc[0], acc[2]); add2(acc[1], acc[3]); add2(acc[0], acc[1]);
        float s = pairsum(acc[0]);
        s += __shfl_xor_sync(0xffffffffu, s, 16);
        if (kh == 0) {
            float pre = s + gin;
            red[cur][row] = (gi == 2) ? ftanh(pre) : sigm(pre);
        }

        if (w != 0) {
            asm volatile("bar.arrive 1, 256;" ::: "memory");
        } else {
            asm volatile("bar.sync 1, 256;" ::: "memory");
            float iv = red[cur][lane],      fv = red[cur][32 + lane];
            float gv = red[cur][64 + lane], ov = red[cur][96 + lane];
            cst = fv * cst + iv * gv;
            float h = ov * ftanh(cst);
            hstage[cur][lane] = h;
            __syncwarp();
            if (st < SEQ - 1) {
                int seg = lane & 3;
                const ulonglong2* sp = reinterpret_cast<const ulonglong2*>(&hstage[cur][0]) + seg * 2;
                ulonglong2 v0 = sp[0], v1 = sp[1];
                uint32_t dst = ra[nxt];
                asm volatile("st.shared::cluster.b64 [%0], %1;" :: "r"(dst      ), "l"(v0.x) : "memory");
                asm volatile("st.shared::cluster.b64 [%0], %1;" :: "r"(dst +  8u), "l"(v0.y) : "memory");
                asm volatile("st.shared::cluster.b64 [%0], %1;" :: "r"(dst + 16u), "l"(v1.x) : "memory");
                asm volatile("st.shared::cluster.b64 [%0], %1;" :: "r"(dst + 24u), "l"(v1.y) : "memory");
                __syncwarp();
                if (lane < 8)
                    asm volatile("st.release.cluster.shared::cluster.u32 [%0], %1;"
                                 :: "r"(fa), "r"((uint32_t)(st + 1)) : "memory");
            }
        }
    }

    __syncthreads();
    if (w == 1) {
        int tp = d ? 0 : (SEQ - 1);
        g_hcat[b * SEQ + tp][d * HID + (int)cig * UPC + lane] = hstage[(SEQ - 1) & 1][lane];
    }

    asm volatile("barrier.cluster.arrive.aligned;" ::: "memory");
    asm volatile("barrier.cluster.wait.aligned;"  ::: "memory");
}

// ------------------------- final assembly -----------------------------------
__global__ void __launch_bounds__(256) assemble_kernel(float* __restrict__ out)
{
    int b = blockIdx.z, k = blockIdx.y, m0 = blockIdx.x * 16;
    int tid = threadIdx.x;
    __shared__ float st_s[SEQ];
    __shared__ float sz_s[NPOS];
    __shared__ float sh_s[16];
    for (int i = tid; i < SEQ; i += 256) st_s[i] = g_stail[b * SEQ + i][k];
    if (tid < NPOS) sz_s[tid] = g_sztab[k][tid];
    if (tid < 16)   sh_s[tid] = g_shead[b * SEQ + m0 + tid][k];
    __syncthreads();

    float* orow = out + (((size_t)(b * NOUT + k)) * SEQ + m0) * SEQ;
    #pragma unroll
    for (int it = 0; it < 8; it++) {
        int lin = it * 256 + tid;
        int r = lin >> 7;
        int n4 = (lin & 127) << 2;
        int m = m0 + r;
        float sh = sh_s[r];
        float4 v;
        int e;
        e = min(max(n4     - m, -15), 14) + 15; v.x = sh + st_s[n4    ] + sz_s[e];
        e = min(max(n4 + 1 - m, -15), 14) + 15; v.y = sh + st_s[n4 + 1] + sz_s[e];
        e = min(max(n4 + 2 - m, -15), 14) + 15; v.z = sh + st_s[n4 + 2] + sz_s[e];
        e = min(max(n4 + 3 - m, -15), 14) + 15; v.w = sh + st_s[n4 + 3] + sz_s[e];
        *reinterpret_cast<float4*>(orow + (size_t)r * SEQ + n4) = v;
    }
}

// ------------------------- launch -------------------------------------------
extern "C" void kernel_launch(void* const* d_in, const int* in_sizes, int n_in,
                              void* d_out, int out_size)
{
    const float* x      = (const float*)d_in[0];
    const float* Wih_f  = (const float*)d_in[1];
    const float* Whh_f  = (const float*)d_in[2];
    const float* bih_f  = (const float*)d_in[3];
    const float* bhh_f  = (const float*)d_in[4];
    const float* Wih_b  = (const float*)d_in[5];
    const float* Whh_b  = (const float*)d_in[6];
    const float* bih_b  = (const float*)d_in[7];
    const float* bhh_b  = (const float*)d_in[8];
    const float* W_head = (const float*)d_in[9];
    const float* b_head = (const float*)d_in[10];
    const float* W_tail = (const float*)d_in[11];
    const float* b_tail = (const float*)d_in[12];
    const float* emb    = (const float*)d_in[13];
    const float* W      = (const float*)d_in[14];
    float* out = (float*)d_out;

    float *pG, *pBias, *pHcat, *pHead, *pTail, *pShead, *pStail;
    cudaGetSymbolAddress((void**)&pG,     g_G);
    cudaGetSymbolAddress((void**)&pBias,  g_bias);
    cudaGetSymbolAddress((void**)&pHcat,  g_hcat);
    cudaGetSymbolAddress((void**)&pHead,  g_head);
    cudaGetSymbolAddress((void**)&pTail,  g_tail);
    cudaGetSymbolAddress((void**)&pShead, g_shead);
    cudaGetSymbolAddress((void**)&pStail, g_stail);

    prep_kernel<<<8, 256>>>(bih_f, bhh_f, bih_b, bhh_b, emb, W);

    // Stage 1: gate input projections, both directions in ONE launch (z)
    gemm_big<<<dim3(G4 / 128, ROWS / 128, 2), 256>>>(
        x, D_IN, Wih_f, Wih_b, D_IN,
        pBias, pBias + G4,
        pG, pG + (size_t)ROWS * G4, 0, G4, D_IN, 0);

    // Stage 2: recurrence (R13)
    lstm_kernel<<<NGRP * CPG, 256>>>(Whh_f, Whh_b);

    // Stage 3: head + tail projections in ONE launch (z), leaky_relu
    gemm_big<<<dim3(MID / 128, ROWS / 128, 2), 256>>>(
        pHcat, MID, W_head, W_tail, MID,
        b_head, b_tail,
        pHead, pTail, 0, MID, MID, 1);

    // Stage 4: biaffine projections (k=50), bias = "ones" column of W
    gemm_tf32<<<dim3(1, ROWS / 64), 128>>>(pHead, MID, W, WLD,
        W + MID, WLD, pShead, NOUT, NOUT, MID, 0);
    gemm_tf32<<<dim3(1, ROWS / 64), 128>>>(pTail, MID, W + (MID + 1), WLD,
        W + (MID + 1) + MID, WLD, pStail, NOUT, NOUT, MID, 0);

    // Stage 5: assemble 210MB output
    assemble_kernel<<<dim3(SEQ / 16, NOUT, NB), 256>>>(out);
}

// round 15
// speedup vs baseline: 1.9660x; 1.1376x over previous
#include <cuda_runtime.h>
#include <cstdint>

#define D_IN 1024
#define HID  256
#define G4   1024
#define MID  512
#define SEQ  512
#define NB   4
#define NOUT 50
#define SED  64
#define NPOS 30
#define WLD  1090           // 2*(MID+1) + SED
#define ROWS 2048           // NB*SEQ
#define CPG  8              // CTAs per recurrence group (== cluster size)
#define UPC  32             // hidden units per CTA
#define NGRP 8              // 2 dirs * 4 batch
#define HPAD 132            // floats per K-half (128 + 4 pad)
#define PSTR (2 * HPAD)     // floats per parity buffer

#define TROW 36             // smem floats per tile row (16B-aligned, conflict-free)
#define TSTR (128 * TROW)   // floats per tile
#define GB_SMEM (4 * TSTR * 4)  // 2 stages x (A+B) bytes = 73728

// ------------------------- scratch (static device memory) -------------------
__device__ float g_G[2][ROWS][G4];      // gate input preactivations (+bias)
__device__ float g_bias[2][G4];
__device__ float g_hcat[ROWS][MID];     // [b*SEQ+t][dir*HID + j]
__device__ float g_head[ROWS][MID];
__device__ float g_tail[ROWS][MID];
__device__ float g_shead[ROWS][NOUT];   // [(b,m)][k]
__device__ float g_stail[ROWS][NOUT];   // [(b,n)][k]
__device__ float g_sztab[NOUT][NPOS];

// ------------------------- prep: bias, size table ---------------------------
__global__ void prep_kernel(const float* __restrict__ bih_f, const float* __restrict__ bhh_f,
                            const float* __restrict__ bih_b, const float* __restrict__ bhh_b,
                            const float* __restrict__ emb,   const float* __restrict__ W)
{
    int g = blockIdx.x * blockDim.x + threadIdx.x;
    if (g < G4)            g_bias[0][g]      = bih_f[g]      + bhh_f[g];
    else if (g < 2 * G4)   g_bias[1][g - G4] = bih_b[g - G4] + bhh_b[g - G4];
    if (g < NOUT * NPOS) {
        int k = g / NPOS, p = g % NPOS;
        float s = 0.f;
        #pragma unroll 8
        for (int h = 0; h < SED; h++)
            s += emb[p * SED + h] * W[k * WLD + 2 * (MID + 1) + h];
        g_sztab[k][p] = s;
    }
}

__device__ __forceinline__ float to_tf32(float x) {
    uint32_t u;
    asm("cvt.rna.tf32.f32 %0, %1;" : "=r"(u) : "f"(x));
    return __uint_as_float(u);
}
__device__ __forceinline__ uint32_t to_tf32u(float x) {
    uint32_t u;
    asm("cvt.rna.tf32.f32 %0, %1;" : "=r"(u) : "f"(x));
    return u;
}

// ------------------------- big tf32 GEMM: cp.async pipelined ----------------
// C_z = A @ B_z^T (+bias_z, opt leaky). 128x128 tiles, 256 threads, 2-stage.
__global__ void __launch_bounds__(256) gemm_big(
    const float* __restrict__ A, int lda,
    const float* __restrict__ B0, const float* __restrict__ B1, int ldb,
    const float* __restrict__ bias0, const float* __restrict__ bias1,
    float* __restrict__ C0, float* __restrict__ C1, int ldc,
    int K, int act)
{
    extern __shared__ float smem[];
    float* Asm = smem;               // [2][128][TROW]
    float* Bsm = smem + 2 * TSTR;    // [2][128][TROW]

    int z = blockIdx.z;
    const float* Bw   = z ? B1 : B0;
    const float* bias = z ? bias1 : bias0;
    float* C = (z ? C1 : C0);

    int tid  = threadIdx.x;
    int warp = tid >> 5, lane = tid & 31;
    int gq = lane >> 2, tg = lane & 3;
    int wm = (warp >> 1) * 32, wn = (warp & 1) * 64;
    int bm = blockIdx.y * 128, bn = blockIdx.x * 128;

    uint32_t sa = (uint32_t)__cvta_generic_to_shared(Asm);
    uint32_t sb = (uint32_t)__cvta_generic_to_shared(Bsm);

    // per-thread load slots: 4 passes, l4 = tid + i*256, r = l4>>3, c4 = (l4&7)*4
    int nk = K >> 5;

    auto issue = [&](int stg, int k0) {
        #pragma unroll
        for (int i = 0; i < 4; i++) {
            int l4 = tid + i * 256;
            int r = l4 >> 3, c4 = (l4 & 7) << 2;
            uint32_t off = (uint32_t)(stg * TSTR + r * TROW + c4) * 4u;
            const float* pa = A  + (size_t)(bm + r) * lda + k0 + c4;
            const float* pb = Bw + (size_t)(bn + r) * ldb + k0 + c4;
            asm volatile("cp.async.cg.shared.global [%0], [%1], 16;"
                         :: "r"(sa + off), "l"(pa));
            asm volatile("cp.async.cg.shared.global [%0], [%1], 16;"
                         :: "r"(sb + off), "l"(pb));
        }
        asm volatile("cp.async.commit_group;" ::: "memory");
    };

    float acc[2][8][4];
    #pragma unroll
    for (int a = 0; a < 2; a++)
        #pragma unroll
        for (int b = 0; b < 8; b++)
            #pragma unroll
            for (int c = 0; c < 4; c++) acc[a][b][c] = 0.f;

    issue(0, 0);

    for (int kc = 0; kc < nk; kc++) {
        if (kc + 1 < nk) {
            issue((kc + 1) & 1, (kc + 1) << 5);
            asm volatile("cp.async.wait_group 1;" ::: "memory");
        } else {
            asm volatile("cp.async.wait_group 0;" ::: "memory");
        }
        __syncthreads();

        const float* At = Asm + (kc & 1) * TSTR;
        const float* Bt = Bsm + (kc & 1) * TSTR;

        #pragma unroll
        for (int kk = 0; kk < 32; kk += 8) {
            uint32_t af[2][4], bf[8][2];
            #pragma unroll
            for (int mf = 0; mf < 2; mf++) {
                int r0 = wm + mf * 16 + gq;
                af[mf][0] = to_tf32u(At[r0 * TROW + kk + tg]);
                af[mf][1] = to_tf32u(At[(r0 + 8) * TROW + kk + tg]);
                af[mf][2] = to_tf32u(At[r0 * TROW + kk + tg + 4]);
                af[mf][3] = to_tf32u(At[(r0 + 8) * TROW + kk + tg + 4]);
            }
            #pragma unroll
            for (int nf = 0; nf < 8; nf++) {
                int n0 = wn + nf * 8 + gq;
                bf[nf][0] = to_tf32u(Bt[n0 * TROW + kk + tg]);
                bf[nf][1] = to_tf32u(Bt[n0 * TROW + kk + tg + 4]);
            }
            #pragma unroll
            for (int mf = 0; mf < 2; mf++)
                #pragma unroll
                for (int nf = 0; nf < 8; nf++)
                    asm volatile(
                        "mma.sync.aligned.m16n8k8.row.col.f32.tf32.tf32.f32 "
                        "{%0,%1,%2,%3}, {%4,%5,%6,%7}, {%8,%9}, {%0,%1,%2,%3};\n"
                        : "+f"(acc[mf][nf][0]), "+f"(acc[mf][nf][1]),
                          "+f"(acc[mf][nf][2]), "+f"(acc[mf][nf][3])
                        : "r"(af[mf][0]), "r"(af[mf][1]), "r"(af[mf][2]), "r"(af[mf][3]),
                          "r"(bf[nf][0]), "r"(bf[nf][1]));
        }
        __syncthreads();
    }

    #pragma unroll
    for (int mf = 0; mf < 2; mf++) {
        #pragma unroll
        for (int nf = 0; nf < 8; nf++) {
            int row = bm + wm + mf * 16 + gq;
            int col = bn + wn + nf * 8 + tg * 2;
            #pragma unroll
            for (int q = 0; q < 4; q++) {
                int r = row + (q >> 1) * 8;
                int c = col + (q & 1);
                float v = acc[mf][nf][q] + bias[c];
                if (act) v = v > 0.f ? v : 0.01f * v;
                C[(size_t)r * ldc + c] = v;
            }
        }
    }
}

// ------------------------- small tf32 GEMM (stage 4, N=50, z-batched) -------
__global__ void __launch_bounds__(128) gemm_small(
    const float* __restrict__ A0, const float* __restrict__ A1, int lda,
    const float* __restrict__ W,  // biaffine weights, row stride WLD
    float* __restrict__ C0, float* __restrict__ C1, int ldc,
    int N, int K)
{
    __shared__ float As[64][33];
    __shared__ float Bs[64][33];
    int z = blockIdx.z;
    const float* A    = z ? A1 : A0;
    const float* Bw   = W + (size_t)z * (MID + 1);
    const float* bias = Bw + MID;     // "ones" column, stride WLD
    float* C = z ? C1 : C0;

    int tid  = threadIdx.x;
    int warp = tid >> 5, lane = tid & 31;
    int gq = lane >> 2, tg = lane & 3;
    int wm = (warp >> 1) * 32, wn = (warp & 1) * 32;
    int bm = blockIdx.y * 64, bn = 0;

    float acc[2][4][4];
    #pragma unroll
    for (int a = 0; a < 2; a++)
        #pragma unroll
        for (int b = 0; b < 4; b++)
            #pragma unroll
            for (int c = 0; c < 4; c++) acc[a][b][c] = 0.f;

    for (int k0 = 0; k0 < K; k0 += 32) {
        #pragma unroll
        for (int i = 0; i < 4; i++) {
            int l4 = tid + i * 128;
            int r = l4 >> 3, c4 = (l4 & 7) << 2;
            const float4 v = *reinterpret_cast<const float4*>(A + (size_t)(bm + r) * lda + k0 + c4);
            As[r][c4 + 0] = to_tf32(v.x); As[r][c4 + 1] = to_tf32(v.y);
            As[r][c4 + 2] = to_tf32(v.z); As[r][c4 + 3] = to_tf32(v.w);
        }
        #pragma unroll
        for (int i = 0; i < 4; i++) {
            int l4 = tid + i * 128;
            int r = l4 >> 3, c4 = (l4 & 7) << 2;
            float4 v = make_float4(0.f, 0.f, 0.f, 0.f);
            if (bn + r < N) {
                const float* p = Bw + (size_t)(bn + r) * WLD + k0 + c4;
                v = make_float4(p[0], p[1], p[2], p[3]);
            }
            Bs[r][c4 + 0] = to_tf32(v.x); Bs[r][c4 + 1] = to_tf32(v.y);
            Bs[r][c4 + 2] = to_tf32(v.z); Bs[r][c4 + 3] = to_tf32(v.w);
        }
        __syncthreads();

        #pragma unroll
        for (int kk = 0; kk < 32; kk += 8) {
            uint32_t af[2][4], bf[4][2];
            #pragma unroll
            for (int mf = 0; mf < 2; mf++) {
                int r0 = wm + mf * 16 + gq;
                af[mf][0] = __float_as_uint(As[r0    ][kk + tg]);
                af[mf][1] = __float_as_uint(As[r0 + 8][kk + tg]);
                af[mf][2] = __float_as_uint(As[r0    ][kk + tg + 4]);
                af[mf][3] = __float_as_uint(As[r0 + 8][kk + tg + 4]);
            }
            #pragma unroll
            for (int nf = 0; nf < 4; nf++) {
                int n0 = wn + nf * 8 + gq;
                bf[nf][0] = __float_as_uint(Bs[n0][kk + tg]);
                bf[nf][1] = __float_as_uint(Bs[n0][kk + tg + 4]);
            }
            #pragma unroll
            for (int mf = 0; mf < 2; mf++)
                #pragma unroll
                for (int nf = 0; nf < 4; nf++)
                    asm volatile(
                        "mma.sync.aligned.m16n8k8.row.col.f32.tf32.tf32.f32 "
                        "{%0,%1,%2,%3}, {%4,%5,%6,%7}, {%8,%9}, {%0,%1,%2,%3};\n"
                        : "+f"(acc[mf][nf][0]), "+f"(acc[mf][nf][1]),
                          "+f"(acc[mf][nf][2]), "+f"(acc[mf][nf][3])
                        : "r"(af[mf][0]), "r"(af[mf][1]), "r"(af[mf][2]), "r"(af[mf][3]),
                          "r"(bf[nf][0]), "r"(bf[nf][1]));
        }
        __syncthreads();
    }

    #pragma unroll
    for (int mf = 0; mf < 2; mf++) {
        #pragma unroll
        for (int nf = 0; nf < 4; nf++) {
            int row = bm + wm + mf * 16 + gq;
            int col = bn + wn + nf * 8 + tg * 2;
            #pragma unroll
            for (int q = 0; q < 4; q++) {
                int r = row + (q >> 1) * 8;
                int c = col + (q & 1);
                if (c < N)
                    C[(size_t)r * ldc + c] = acc[mf][nf][q] + bias[(size_t)c * WLD];
            }
        }
    }
}

// ------------------------- LSTM recurrence (R13, unchanged) -----------------
__device__ __forceinline__ float sigm(float x) { return 1.f / (1.f + __expf(-x)); }
__device__ __forceinline__ float ftanh(float x) {
    float e = __expf(2.f * x);
    return 1.f - __fdividef(2.f, e + 1.f);
}
__device__ __forceinline__ void fma2(unsigned long long& acc,
                                     unsigned long long a, unsigned long long b) {
    asm("fma.rn.f32x2 %0, %1, %2, %0;" : "+l"(acc) : "l"(a), "l"(b));
}
__device__ __forceinline__ void add2(unsigned long long& a, unsigned long long b) {
    asm("add.rn.f32x2 %0, %0, %1;" : "+l"(a) : "l"(b));
}
__device__ __forceinline__ float pairsum(unsigned long long p) {
    uint32_t lo, hi;
    asm("mov.b64 {%0,%1}, %2;" : "=r"(lo), "=r"(hi) : "l"(p));
    return __uint_as_float(lo) + __uint_as_float(hi);
}

__global__ void __launch_bounds__(256, 1) __cluster_dims__(CPG, 1, 1)
lstm_kernel(const float* __restrict__ Whh_f, const float* __restrict__ Whh_b)
{
    __shared__ __align__(16) float    hs2[2][PSTR];
    __shared__ __align__(16) float    red[2][128];
    __shared__ __align__(16) float    hstage[2][UPC];
    __shared__ __align__(16) uint32_t flags[CPG];

    int grp = blockIdx.x / CPG;
    uint32_t cig;
    asm("mov.u32 %0, %%cluster_ctarank;" : "=r"(cig));
    int d = grp >> 2, b = grp & 3;
    int tid  = threadIdx.x;
    int w    = tid >> 5;
    int lane = tid & 31;
    int row  = w * 16 + (lane & 15);
    int kh   = lane >> 4;
    int gi   = row >> 5;
    int ul   = row & 31;
    int j    = (int)cig * UPC + ul;
    int grow = gi * HID + j;
    const float* Whh = d ? Whh_b : Whh_f;
    const float* Gd  = &g_G[d][0][0];

    ulonglong2 w2[32];
    #pragma unroll
    for (int q = 0; q < 32; q++)
        w2[q] = *reinterpret_cast<const ulonglong2*>(
            &Whh[(size_t)grow * HID + kh * 128 + q * 4]);

    for (int i = tid; i < 2 * PSTR; i += 256) ((float*)hs2)[i] = 0.f;
    if (tid < CPG) flags[tid] = 0u;
    __syncthreads();
    asm volatile("barrier.cluster.arrive.aligned;" ::: "memory");
    asm volatile("barrier.cluster.wait.aligned;"  ::: "memory");

    uint32_t hs_u32  = (uint32_t)__cvta_generic_to_shared(&hs2[0][0]);
    uint32_t flg_u32 = (uint32_t)__cvta_generic_to_shared(&flags[0]);
    uint32_t my_flag_addr = flg_u32 + (uint32_t)(lane & 7) * 4u;

    int ds = (int)cig * UPC + ((int)cig >= 4 ? 4 : 0);
    uint32_t ra[2];
    {
        int rnk = (lane >> 2) & 7, seg = lane & 3;
        #pragma unroll
        for (int P = 0; P < 2; P++) {
            uint32_t laddr = hs_u32 + (uint32_t)(P * PSTR + ds) * 4u + (uint32_t)seg * 32u;
            asm("mapa.shared::cluster.u32 %0, %1, %2;"
                : "=r"(ra[P]) : "r"(laddr), "r"(rnk));
        }
    }
    uint32_t fa;
    {
        uint32_t laddr = flg_u32 + cig * 4u;
        asm("mapa.shared::cluster.u32 %0, %1, %2;"
            : "=r"(fa) : "r"(laddr), "r"(lane & 7));
    }

    float cst = 0.f;

    for (int st = 0; st < SEQ; st++) {
        int t = d ? (SEQ - 1 - st) : st;
        int cur = st & 1, nxt = cur ^ 1;

        float gin = 0.f;
        if (kh == 0)
            gin = __ldg(&Gd[(size_t)(b * SEQ + t) * G4 + grow]);

        {
            uint32_t tgt = (uint32_t)st;
            while (true) {
                uint32_t f = 0xffffffffu;
                if (lane < 8)
                    asm volatile("ld.volatile.shared.u32 %0, [%1];"
                                 : "=r"(f) : "r"(my_flag_addr));
                if (__all_sync(0xffffffffu, f >= tgt)) break;
            }
            if (lane < 8) {
                uint32_t f2;
                asm volatile("ld.acquire.cluster.shared::cta.u32 %0, [%1];"
                             : "=r"(f2) : "r"(my_flag_addr));
            }
        }

        if (w == 1 && st > 0) {
            int tp = d ? (SEQ - st) : (st - 1);
            g_hcat[b * SEQ + tp][d * HID + (int)cig * UPC + lane] = hstage[(st - 1) & 1][lane];
        }

        const float* hb = &hs2[cur][kh * HPAD];
        unsigned long long acc[4] = {0ull, 0ull, 0ull, 0ull};
        #pragma unroll
        for (int q = 0; q < 32; q++) {
            const ulonglong2 hv = *reinterpret_cast<const ulonglong2*>(hb + q * 4);
            fma2(acc[q & 3], w2[q].x, hv.x);
            fma2(acc[q & 3], w2[q].y, hv.y);
        }
        add2(acc[0], acc[2]); add2(acc[1], acc[3]); add2(acc[0], acc[1]);
        float s = pairsum(acc[0]);
        s += __shfl_xor_sync(0xffffffffu, s, 16);
        if (kh == 0) {
            float pre = s + gin;
            red[cur][row] = (gi == 2) ? ftanh(pre) : sigm(pre);
        }

        if (w != 0) {
            asm volatile("bar.arrive 1, 256;" ::: "memory");
        } else {
            asm volatile("bar.sync 1, 256;" ::: "memory");
            float iv = red[cur][lane],      fv = red[cur][32 + lane];
            float gv = red[cur][64 + lane], ov = red[cur][96 + lane];
            cst = fv * cst + iv * gv;
            float h = ov * ftanh(cst);
            hstage[cur][lane] = h;
            __syncwarp();
            if (st < SEQ - 1) {
                int seg = lane & 3;
                const ulonglong2* sp = reinterpret_cast<const ulonglong2*>(&hstage[cur][0]) + seg * 2;
                ulonglong2 v0 = sp[0], v1 = sp[1];
                uint32_t dst = ra[nxt];
                asm volatile("st.shared::cluster.b64 [%0], %1;" :: "r"(dst      ), "l"(v0.x) : "memory");
                asm volatile("st.shared::cluster.b64 [%0], %1;" :: "r"(dst +  8u), "l"(v0.y) : "memory");
                asm volatile("st.shared::cluster.b64 [%0], %1;" :: "r"(dst + 16u), "l"(v1.x) : "memory");
                asm volatile("st.shared::cluster.b64 [%0], %1;" :: "r"(dst + 24u), "l"(v1.y) : "memory");
                __syncwarp();
                if (lane < 8)
                    asm volatile("st.release.cluster.shared::cluster.u32 [%0], %1;"
                                 :: "r"(fa), "r"((uint32_t)(st + 1)) : "memory");
            }
        }
    }

    __syncthreads();
    if (w == 1) {
        int tp = d ? 0 : (SEQ - 1);
        g_hcat[b * SEQ + tp][d * HID + (int)cig * UPC + lane] = hstage[(SEQ - 1) & 1][lane];
    }

    asm volatile("barrier.cluster.arrive.aligned;" ::: "memory");
    asm volatile("barrier.cluster.wait.aligned;"  ::: "memory");
}

// ------------------------- final assembly -----------------------------------
__global__ void __launch_bounds__(256) assemble_kernel(float* __restrict__ out)
{
    int b = blockIdx.z, k = blockIdx.y, m0 = blockIdx.x * 16;
    int tid = threadIdx.x;
    __shared__ float st_s[SEQ];
    __shared__ float sz_s[NPOS];
    __shared__ float sh_s[16];
    for (int i = tid; i < SEQ; i += 256) st_s[i] = g_stail[b * SEQ + i][k];
    if (tid < NPOS) sz_s[tid] = g_sztab[k][tid];
    if (tid < 16)   sh_s[tid] = g_shead[b * SEQ + m0 + tid][k];
    __syncthreads();

    float* orow = out + (((size_t)(b * NOUT + k)) * SEQ + m0) * SEQ;
    #pragma unroll
    for (int it = 0; it < 8; it++) {
        int lin = it * 256 + tid;
        int r = lin >> 7;
        int n4 = (lin & 127) << 2;
        int m = m0 + r;
        float sh = sh_s[r];
        float4 v;
        int e;
        e = min(max(n4     - m, -15), 14) + 15; v.x = sh + st_s[n4    ] + sz_s[e];
        e = min(max(n4 + 1 - m, -15), 14) + 15; v.y = sh + st_s[n4 + 1] + sz_s[e];
        e = min(max(n4 + 2 - m, -15), 14) + 15; v.z = sh + st_s[n4 + 2] + sz_s[e];
        e = min(max(n4 + 3 - m, -15), 14) + 15; v.w = sh + st_s[n4 + 3] + sz_s[e];
        *reinterpret_cast<float4*>(orow + (size_t)r * SEQ + n4) = v;
    }
}

// ------------------------- launch -------------------------------------------
extern "C" void kernel_launch(void* const* d_in, const int* in_sizes, int n_in,
                              void* d_out, int out_size)
{
    const float* x      = (const float*)d_in[0];
    const float* Wih_f  = (const float*)d_in[1];
    const float* Whh_f  = (const float*)d_in[2];
    const float* bih_f  = (const float*)d_in[3];
    const float* bhh_f  = (const float*)d_in[4];
    const float* Wih_b  = (const float*)d_in[5];
    const float* Whh_b  = (const float*)d_in[6];
    const float* bih_b  = (const float*)d_in[7];
    const float* bhh_b  = (const float*)d_in[8];
    const float* W_head = (const float*)d_in[9];
    const float* b_head = (const float*)d_in[10];
    const float* W_tail = (const float*)d_in[11];
    const float* b_tail = (const float*)d_in[12];
    const float* emb    = (const float*)d_in[13];
    const float* W      = (const float*)d_in[14];
    float* out = (float*)d_out;

    float *pG, *pBias, *pHcat, *pHead, *pTail, *pShead, *pStail;
    cudaGetSymbolAddress((void**)&pG,     g_G);
    cudaGetSymbolAddress((void**)&pBias,  g_bias);
    cudaGetSymbolAddress((void**)&pHcat,  g_hcat);
    cudaGetSymbolAddress((void**)&pHead,  g_head);
    cudaGetSymbolAddress((void**)&pTail,  g_tail);
    cudaGetSymbolAddress((void**)&pShead, g_shead);
    cudaGetSymbolAddress((void**)&pStail, g_stail);

    cudaFuncSetAttribute(gemm_big,
                         cudaFuncAttributeMaxDynamicSharedMemorySize, GB_SMEM);

    prep_kernel<<<8, 256>>>(bih_f, bhh_f, bih_b, bhh_b, emb, W);

    // Stage 1: gate input projections, both directions in ONE launch (z)
    gemm_big<<<dim3(G4 / 128, ROWS / 128, 2), 256, GB_SMEM>>>(
        x, D_IN, Wih_f, Wih_b, D_IN,
        pBias, pBias + G4,
        pG, pG + (size_t)ROWS * G4, G4, D_IN, 0);

    // Stage 2: recurrence (R13)
    lstm_kernel<<<NGRP * CPG, 256>>>(Whh_f, Whh_b);

    // Stage 3: head + tail projections in ONE launch (z), leaky_relu
    gemm_big<<<dim3(MID / 128, ROWS / 128, 2), 256, GB_SMEM>>>(
        pHcat, MID, W_head, W_tail, MID,
        b_head, b_tail,
        pHead, pTail, MID, MID, 1);

    // Stage 4: biaffine projections (k=50), head+tail z-batched
    gemm_small<<<dim3(1, ROWS / 64, 2), 128>>>(
        pHead, pTail, MID, W, pShead, pStail, NOUT, NOUT, MID);

    // Stage 5: assemble 210MB output
    assemble_kernel<<<dim3(SEQ / 16, NOUT, NB), 256>>>(out);
}

// round 16
// speedup vs baseline: 2.3012x; 1.1705x over previous
#include <cuda_runtime.h>
#include <cstdint>

#define D_IN 1024
#define HID  256
#define G4   1024
#define MID  512
#define SEQ  512
#define NB   4
#define NOUT 50
#define SED  64
#define NPOS 30
#define WLD  1090           // 2*(MID+1) + SED
#define ROWS 2048           // NB*SEQ
#define CPG  8              // CTAs per recurrence group (== cluster size)
#define UPC  32             // hidden units per CTA
#define NGRP 8              // 2 dirs * 4 batch
#define HPAD 132            // floats per K-half (128 + 4 pad)
#define PSTR (2 * HPAD)     // floats per parity buffer

#define TROW 36             // smem floats per tile row (16B-aligned, conflict-free)
#define TSTR (128 * TROW)   // floats per tile
#define GB_SMEM (4 * TSTR * 4)  // 2 stages x (A+B) bytes = 73728

// ------------------------- scratch (static device memory) -------------------
__device__ float g_G[2][ROWS][G4];      // gate input preactivations (+bias)
__device__ float g_bias[2][G4];
__device__ float g_hcat[ROWS][MID];     // [b*SEQ+t][dir*HID + j]
__device__ float g_head[ROWS][MID];
__device__ float g_tail[ROWS][MID];
__device__ float g_shead[ROWS][NOUT];   // [(b,m)][k]
__device__ float g_stail[ROWS][NOUT];   // [(b,n)][k]
__device__ float g_sztab[NOUT][NPOS];

// ------------------------- prep: bias, size table ---------------------------
__global__ void prep_kernel(const float* __restrict__ bih_f, const float* __restrict__ bhh_f,
                            const float* __restrict__ bih_b, const float* __restrict__ bhh_b,
                            const float* __restrict__ emb,   const float* __restrict__ W)
{
    int g = blockIdx.x * blockDim.x + threadIdx.x;
    if (g < G4)            g_bias[0][g]      = bih_f[g]      + bhh_f[g];
    else if (g < 2 * G4)   g_bias[1][g - G4] = bih_b[g - G4] + bhh_b[g - G4];
    if (g < NOUT * NPOS) {
        int k = g / NPOS, p = g % NPOS;
        float s = 0.f;
        #pragma unroll 8
        for (int h = 0; h < SED; h++)
            s += emb[p * SED + h] * W[k * WLD + 2 * (MID + 1) + h];
        g_sztab[k][p] = s;
    }
}

__device__ __forceinline__ float to_tf32(float x) {
    uint32_t u;
    asm("cvt.rna.tf32.f32 %0, %1;" : "=r"(u) : "f"(x));
    return __uint_as_float(u);
}
__device__ __forceinline__ uint32_t to_tf32u(float x) {
    uint32_t u;
    asm("cvt.rna.tf32.f32 %0, %1;" : "=r"(u) : "f"(x));
    return u;
}

// ------------------------- big tf32 GEMM: cp.async pipelined ----------------
__global__ void __launch_bounds__(256) gemm_big(
    const float* __restrict__ A, int lda,
    const float* __restrict__ B0, const float* __restrict__ B1, int ldb,
    const float* __restrict__ bias0, const float* __restrict__ bias1,
    float* __restrict__ C0, float* __restrict__ C1, int ldc,
    int K, int act)
{
    extern __shared__ float smem[];
    float* Asm = smem;               // [2][128][TROW]
    float* Bsm = smem + 2 * TSTR;    // [2][128][TROW]

    int z = blockIdx.z;
    const float* Bw   = z ? B1 : B0;
    const float* bias = z ? bias1 : bias0;
    float* C = (z ? C1 : C0);

    int tid  = threadIdx.x;
    int warp = tid >> 5, lane = tid & 31;
    int gq = lane >> 2, tg = lane & 3;
    int wm = (warp >> 1) * 32, wn = (warp & 1) * 64;
    int bm = blockIdx.y * 128, bn = blockIdx.x * 128;

    uint32_t sa = (uint32_t)__cvta_generic_to_shared(Asm);
    uint32_t sb = (uint32_t)__cvta_generic_to_shared(Bsm);

    int nk = K >> 5;

    auto issue = [&](int stg, int k0) {
        #pragma unroll
        for (int i = 0; i < 4; i++) {
            int l4 = tid + i * 256;
            int r = l4 >> 3, c4 = (l4 & 7) << 2;
            uint32_t off = (uint32_t)(stg * TSTR + r * TROW + c4) * 4u;
            const float* pa = A  + (size_t)(bm + r) * lda + k0 + c4;
            const float* pb = Bw + (size_t)(bn + r) * ldb + k0 + c4;
            asm volatile("cp.async.cg.shared.global [%0], [%1], 16;"
                         :: "r"(sa + off), "l"(pa));
            asm volatile("cp.async.cg.shared.global [%0], [%1], 16;"
                         :: "r"(sb + off), "l"(pb));
        }
        asm volatile("cp.async.commit_group;" ::: "memory");
    };

    float acc[2][8][4];
    #pragma unroll
    for (int a = 0; a < 2; a++)
        #pragma unroll
        for (int b = 0; b < 8; b++)
            #pragma unroll
            for (int c = 0; c < 4; c++) acc[a][b][c] = 0.f;

    issue(0, 0);

    for (int kc = 0; kc < nk; kc++) {
        if (kc + 1 < nk) {
            issue((kc + 1) & 1, (kc + 1) << 5);
            asm volatile("cp.async.wait_group 1;" ::: "memory");
        } else {
            asm volatile("cp.async.wait_group 0;" ::: "memory");
        }
        __syncthreads();

        const float* At = Asm + (kc & 1) * TSTR;
        const float* Bt = Bsm + (kc & 1) * TSTR;

        #pragma unroll
        for (int kk = 0; kk < 32; kk += 8) {
            uint32_t af[2][4], bf[8][2];
            #pragma unroll
            for (int mf = 0; mf < 2; mf++) {
                int r0 = wm + mf * 16 + gq;
                af[mf][0] = to_tf32u(At[r0 * TROW + kk + tg]);
                af[mf][1] = to_tf32u(At[(r0 + 8) * TROW + kk + tg]);
                af[mf][2] = to_tf32u(At[r0 * TROW + kk + tg + 4]);
                af[mf][3] = to_tf32u(At[(r0 + 8) * TROW + kk + tg + 4]);
            }
            #pragma unroll
            for (int nf = 0; nf < 8; nf++) {
                int n0 = wn + nf * 8 + gq;
                bf[nf][0] = to_tf32u(Bt[n0 * TROW + kk + tg]);
                bf[nf][1] = to_tf32u(Bt[n0 * TROW + kk + tg + 4]);
            }
            #pragma unroll
            for (int mf = 0; mf < 2; mf++)
                #pragma unroll
                for (int nf = 0; nf < 8; nf++)
                    asm volatile(
                        "mma.sync.aligned.m16n8k8.row.col.f32.tf32.tf32.f32 "
                        "{%0,%1,%2,%3}, {%4,%5,%6,%7}, {%8,%9}, {%0,%1,%2,%3};\n"
                        : "+f"(acc[mf][nf][0]), "+f"(acc[mf][nf][1]),
                          "+f"(acc[mf][nf][2]), "+f"(acc[mf][nf][3])
                        : "r"(af[mf][0]), "r"(af[mf][1]), "r"(af[mf][2]), "r"(af[mf][3]),
                          "r"(bf[nf][0]), "r"(bf[nf][1]));
        }
        __syncthreads();
    }

    #pragma unroll
    for (int mf = 0; mf < 2; mf++) {
        #pragma unroll
        for (int nf = 0; nf < 8; nf++) {
            int row = bm + wm + mf * 16 + gq;
            int col = bn + wn + nf * 8 + tg * 2;
            #pragma unroll
            for (int q = 0; q < 4; q++) {
                int r = row + (q >> 1) * 8;
                int c = col + (q & 1);
                float v = acc[mf][nf][q] + bias[c];
                if (act) v = v > 0.f ? v : 0.01f * v;
                C[(size_t)r * ldc + c] = v;
            }
        }
    }
}

// ------------------------- small tf32 GEMM (stage 4, N=50, z-batched) -------
__global__ void __launch_bounds__(128) gemm_small(
    const float* __restrict__ A0, const float* __restrict__ A1, int lda,
    const float* __restrict__ W,  // biaffine weights, row stride WLD
    float* __restrict__ C0, float* __restrict__ C1, int ldc,
    int N, int K)
{
    __shared__ float As[64][33];
    __shared__ float Bs[64][33];
    int z = blockIdx.z;
    const float* A    = z ? A1 : A0;
    const float* Bw   = W + (size_t)z * (MID + 1);
    const float* bias = Bw + MID;     // "ones" column, stride WLD
    float* C = z ? C1 : C0;

    int tid  = threadIdx.x;
    int warp = tid >> 5, lane = tid & 31;
    int gq = lane >> 2, tg = lane & 3;
    int wm = (warp >> 1) * 32, wn = (warp & 1) * 32;
    int bm = blockIdx.y * 64, bn = 0;

    float acc[2][4][4];
    #pragma unroll
    for (int a = 0; a < 2; a++)
        #pragma unroll
        for (int b = 0; b < 4; b++)
            #pragma unroll
            for (int c = 0; c < 4; c++) acc[a][b][c] = 0.f;

    for (int k0 = 0; k0 < K; k0 += 32) {
        #pragma unroll
        for (int i = 0; i < 4; i++) {
            int l4 = tid + i * 128;
            int r = l4 >> 3, c4 = (l4 & 7) << 2;
            const float4 v = *reinterpret_cast<const float4*>(A + (size_t)(bm + r) * lda + k0 + c4);
            As[r][c4 + 0] = to_tf32(v.x); As[r][c4 + 1] = to_tf32(v.y);
            As[r][c4 + 2] = to_tf32(v.z); As[r][c4 + 3] = to_tf32(v.w);
        }
        #pragma unroll
        for (int i = 0; i < 4; i++) {
            int l4 = tid + i * 128;
            int r = l4 >> 3, c4 = (l4 & 7) << 2;
            float4 v = make_float4(0.f, 0.f, 0.f, 0.f);
            if (bn + r < N) {
                const float* p = Bw + (size_t)(bn + r) * WLD + k0 + c4;
                v = make_float4(p[0], p[1], p[2], p[3]);
            }
            Bs[r][c4 + 0] = to_tf32(v.x); Bs[r][c4 + 1] = to_tf32(v.y);
            Bs[r][c4 + 2] = to_tf32(v.z); Bs[r][c4 + 3] = to_tf32(v.w);
        }
        __syncthreads();

        #pragma unroll
        for (int kk = 0; kk < 32; kk += 8) {
            uint32_t af[2][4], bf[4][2];
            #pragma unroll
            for (int mf = 0; mf < 2; mf++) {
                int r0 = wm + mf * 16 + gq;
                af[mf][0] = __float_as_uint(As[r0    ][kk + tg]);
                af[mf][1] = __float_as_uint(As[r0 + 8][kk + tg]);
                af[mf][2] = __float_as_uint(As[r0    ][kk + tg + 4]);
                af[mf][3] = __float_as_uint(As[r0 + 8][kk + tg + 4]);
            }
            #pragma unroll
            for (int nf = 0; nf < 4; nf++) {
                int n0 = wn + nf * 8 + gq;
                bf[nf][0] = __float_as_uint(Bs[n0][kk + tg]);
                bf[nf][1] = __float_as_uint(Bs[n0][kk + tg + 4]);
            }
            #pragma unroll
            for (int mf = 0; mf < 2; mf++)
                #pragma unroll
                for (int nf = 0; nf < 4; nf++)
                    asm volatile(
                        "mma.sync.aligned.m16n8k8.row.col.f32.tf32.tf32.f32 "
                        "{%0,%1,%2,%3}, {%4,%5,%6,%7}, {%8,%9}, {%0,%1,%2,%3};\n"
                        : "+f"(acc[mf][nf][0]), "+f"(acc[mf][nf][1]),
                          "+f"(acc[mf][nf][2]), "+f"(acc[mf][nf][3])
                        : "r"(af[mf][0]), "r"(af[mf][1]), "r"(af[mf][2]), "r"(af[mf][3]),
                          "r"(bf[nf][0]), "r"(bf[nf][1]));
        }
        __syncthreads();
    }

    #pragma unroll
    for (int mf = 0; mf < 2; mf++) {
        #pragma unroll
        for (int nf = 0; nf < 4; nf++) {
            int row = bm + wm + mf * 16 + gq;
            int col = bn + wn + nf * 8 + tg * 2;
            #pragma unroll
            for (int q = 0; q < 4; q++) {
                int r = row + (q >> 1) * 8;
                int c = col + (q & 1);
                if (c < N)
                    C[(size_t)r * ldc + c] = acc[mf][nf][q] + bias[(size_t)c * WLD];
            }
        }
    }
}

// ------------------------- LSTM recurrence (st.async handoff) ---------------
// R13 structure, but the handoff uses st.async.shared::cluster with
// mbarrier::complete_tx: the remote data store IS the sync signal. No flags,
// no st.release drain, no acquire loads. mbar[2] parity-indexed, count=1;
// warp0 lane0 arms mbar[nxt] with expect_tx(1024) each step; consumers
// try_wait.parity.acquire.cluster on mbar[cur].
__device__ __forceinline__ float sigm(float x) { return 1.f / (1.f + __expf(-x)); }
__device__ __forceinline__ float ftanh(float x) {
    float e = __expf(2.f * x);
    return 1.f - __fdividef(2.f, e + 1.f);
}
__device__ __forceinline__ void fma2(unsigned long long& acc,
                                     unsigned long long a, unsigned long long b) {
    asm("fma.rn.f32x2 %0, %1, %2, %0;" : "+l"(acc) : "l"(a), "l"(b));
}
__device__ __forceinline__ void add2(unsigned long long& a, unsigned long long b) {
    asm("add.rn.f32x2 %0, %0, %1;" : "+l"(a) : "l"(b));
}
__device__ __forceinline__ float pairsum(unsigned long long p) {
    uint32_t lo, hi;
    asm("mov.b64 {%0,%1}, %2;" : "=r"(lo), "=r"(hi) : "l"(p));
    return __uint_as_float(lo) + __uint_as_float(hi);
}

__global__ void __launch_bounds__(256, 1) __cluster_dims__(CPG, 1, 1)
lstm_kernel(const float* __restrict__ Whh_f, const float* __restrict__ Whh_b)
{
    __shared__ __align__(16) float    hs2[2][PSTR];
    __shared__ __align__(16) float    red[2][128];
    __shared__ __align__(16) float    hstage[2][UPC];
    __shared__ __align__(8)  unsigned long long mbar[2];

    int grp = blockIdx.x / CPG;
    uint32_t cig;
    asm("mov.u32 %0, %%cluster_ctarank;" : "=r"(cig));
    int d = grp >> 2, b = grp & 3;
    int tid  = threadIdx.x;
    int w    = tid >> 5;
    int lane = tid & 31;
    int row  = w * 16 + (lane & 15);
    int kh   = lane >> 4;
    int gi   = row >> 5;
    int ul   = row & 31;
    int j    = (int)cig * UPC + ul;
    int grow = gi * HID + j;
    const float* Whh = d ? Whh_b : Whh_f;
    const float* Gd  = &g_G[d][0][0];

    ulonglong2 w2[32];
    #pragma unroll
    for (int q = 0; q < 32; q++)
        w2[q] = *reinterpret_cast<const ulonglong2*>(
            &Whh[(size_t)grow * HID + kh * 128 + q * 4]);

    uint32_t mbar_u32 = (uint32_t)__cvta_generic_to_shared(&mbar[0]);
    for (int i = tid; i < 2 * PSTR; i += 256) ((float*)hs2)[i] = 0.f;
    if (tid < 2)
        asm volatile("mbarrier.init.shared.b64 [%0], %1;"
                     :: "r"(mbar_u32 + tid * 8u), "r"(1) : "memory");
    __syncthreads();
    asm volatile("barrier.cluster.arrive.aligned;" ::: "memory");
    asm volatile("barrier.cluster.wait.aligned;"  ::: "memory");

    uint32_t hs_u32 = (uint32_t)__cvta_generic_to_shared(&hs2[0][0]);

    // push dst: this CTA's 32-float slot in each rank's hs2, split 4x32B;
    // remote mbar addresses per parity for this lane's rank.
    int ds = (int)cig * UPC + ((int)cig >= 4 ? 4 : 0);
    uint32_t ra[2], rm[2];
    {
        int rnk = (lane >> 2) & 7, seg = lane & 3;
        #pragma unroll
        for (int P = 0; P < 2; P++) {
            uint32_t laddr = hs_u32 + (uint32_t)(P * PSTR + ds) * 4u + (uint32_t)seg * 32u;
            asm("mapa.shared::cluster.u32 %0, %1, %2;"
                : "=r"(ra[P]) : "r"(laddr), "r"(rnk));
            asm("mapa.shared::cluster.u32 %0, %1, %2;"
                : "=r"(rm[P]) : "r"(mbar_u32 + (uint32_t)P * 8u), "r"(rnk));
        }
    }

    float cst = 0.f;
    uint32_t ph0 = 0, ph1 = 0;

    for (int st = 0; st < SEQ; st++) {
        int t = d ? (SEQ - 1 - st) : st;
        int cur = st & 1, nxt = cur ^ 1;

        float gin = 0.f;
        if (kh == 0)
            gin = __ldg(&Gd[(size_t)(b * SEQ + t) * G4 + grow]);

        // wait for step st-1's pushes (mbar[cur]); st=0 passes (zeros preloaded)
        if (st > 0) {
            uint32_t mb  = mbar_u32 + (uint32_t)cur * 8u;
            uint32_t par = cur ? ph1 : ph0;
            asm volatile(
                "{.reg .pred P1;\n\t"
                "LAB_%=: mbarrier.try_wait.parity.acquire.cluster.shared::cta.b64 P1, [%0], %1, 0x989680;\n\t"
                "@P1 bra DONE_%=;\n\t"
                "bra LAB_%=;\n\t"
                "DONE_%=:}\n"
                :: "r"(mb), "r"(par) : "memory");
            if (cur) ph1 ^= 1; else ph0 ^= 1;
        }

        if (w == 1 && st > 0) {
            int tp = d ? (SEQ - st) : (st - 1);
            g_hcat[b * SEQ + tp][d * HID + (int)cig * UPC + lane] = hstage[(st - 1) & 1][lane];
        }

        const float* hb = &hs2[cur][kh * HPAD];
        unsigned long long acc[4] = {0ull, 0ull, 0ull, 0ull};
        #pragma unroll
        for (int q = 0; q < 32; q++) {
            const ulonglong2 hv = *reinterpret_cast<const ulonglong2*>(hb + q * 4);
            fma2(acc[q & 3], w2[q].x, hv.x);
            fma2(acc[q & 3], w2[q].y, hv.y);
        }
        add2(acc[0], acc[2]); add2(acc[1], acc[3]); add2(acc[0], acc[1]);
        float s = pairsum(acc[0]);
        s += __shfl_xor_sync(0xffffffffu, s, 16);
        if (kh == 0) {
            float pre = s + gin;
            red[cur][row] = (gi == 2) ? ftanh(pre) : sigm(pre);
        }

        if (w != 0) {
            asm volatile("bar.arrive 1, 256;" ::: "memory");
        } else {
            asm volatile("bar.sync 1, 256;" ::: "memory");
            // arm next parity's mbarrier: 8 ranks x 128B inbound = 1024 bytes
            if (lane == 0 && st < SEQ - 1)
                asm volatile("mbarrier.arrive.expect_tx.shared.b64 _, [%0], %1;"
                             :: "r"(mbar_u32 + (uint32_t)nxt * 8u), "r"(1024) : "memory");
            float iv = red[cur][lane],      fv = red[cur][32 + lane];
            float gv = red[cur][64 + lane], ov = red[cur][96 + lane];
            cst = fv * cst + iv * gv;
            float h = ov * ftanh(cst);
            hstage[cur][lane] = h;
            __syncwarp();
            if (st < SEQ - 1) {
                int seg = lane & 3;
                const ulonglong2* sp = reinterpret_cast<const ulonglong2*>(&hstage[cur][0]) + seg * 2;
                ulonglong2 v0 = sp[0], v1 = sp[1];
                uint32_t dst = ra[nxt], mbr = rm[nxt];
                asm volatile("st.async.shared::cluster.mbarrier::complete_tx::bytes.b64 [%0], %1, [%2];"
                             :: "r"(dst      ), "l"(v0.x), "r"(mbr) : "memory");
                asm volatile("st.async.shared::cluster.mbarrier::complete_tx::bytes.b64 [%0], %1, [%2];"
                             :: "r"(dst +  8u), "l"(v0.y), "r"(mbr) : "memory");
                asm volatile("st.async.shared::cluster.mbarrier::complete_tx::bytes.b64 [%0], %1, [%2];"
                             :: "r"(dst + 16u), "l"(v1.x), "r"(mbr) : "memory");
                asm volatile("st.async.shared::cluster.mbarrier::complete_tx::bytes.b64 [%0], %1, [%2];"
                             :: "r"(dst + 24u), "l"(v1.y), "r"(mbr) : "memory");
            }
        }
    }

    __syncthreads();
    if (w == 1) {
        int tp = d ? 0 : (SEQ - 1);
        g_hcat[b * SEQ + tp][d * HID + (int)cig * UPC + lane] = hstage[(SEQ - 1) & 1][lane];
    }

    asm volatile("barrier.cluster.arrive.aligned;" ::: "memory");
    asm volatile("barrier.cluster.wait.aligned;"  ::: "memory");
}

// ------------------------- final assembly -----------------------------------
__global__ void __launch_bounds__(256) assemble_kernel(float* __restrict__ out)
{
    int b = blockIdx.z, k = blockIdx.y, m0 = blockIdx.x * 16;
    int tid = threadIdx.x;
    __shared__ float st_s[SEQ];
    __shared__ float sz_s[NPOS];
    __shared__ float sh_s[16];
    for (int i = tid; i < SEQ; i += 256) st_s[i] = g_stail[b * SEQ + i][k];
    if (tid < NPOS) sz_s[tid] = g_sztab[k][tid];
    if (tid < 16)   sh_s[tid] = g_shead[b * SEQ + m0 + tid][k];
    __syncthreads();

    float* orow = out + (((size_t)(b * NOUT + k)) * SEQ + m0) * SEQ;
    #pragma unroll
    for (int it = 0; it < 8; it++) {
        int lin = it * 256 + tid;
        int r = lin >> 7;
        int n4 = (lin & 127) << 2;
        int m = m0 + r;
        float sh = sh_s[r];
        float4 v;
        int e;
        e = min(max(n4     - m, -15), 14) + 15; v.x = sh + st_s[n4    ] + sz_s[e];
        e = min(max(n4 + 1 - m, -15), 14) + 15; v.y = sh + st_s[n4 + 1] + sz_s[e];
        e = min(max(n4 + 2 - m, -15), 14) + 15; v.z = sh + st_s[n4 + 2] + sz_s[e];
        e = min(max(n4 + 3 - m, -15), 14) + 15; v.w = sh + st_s[n4 + 3] + sz_s[e];
        *reinterpret_cast<float4*>(orow + (size_t)r * SEQ + n4) = v;
    }
}

// ------------------------- launch -------------------------------------------
extern "C" void kernel_launch(void* const* d_in, const int* in_sizes, int n_in,
                              void* d_out, int out_size)
{
    const float* x      = (const float*)d_in[0];
    const float* Wih_f  = (const float*)d_in[1];
    const float* Whh_f  = (const float*)d_in[2];
    const float* bih_f  = (const float*)d_in[3];
    const float* bhh_f  = (const float*)d_in[4];
    const float* Wih_b  = (const float*)d_in[5];
    const float* Whh_b  = (const float*)d_in[6];
    const float* bih_b  = (const float*)d_in[7];
    const float* bhh_b  = (const float*)d_in[8];
    const float* W_head = (const float*)d_in[9];
    const float* b_head = (const float*)d_in[10];
    const float* W_tail = (const float*)d_in[11];
    const float* b_tail = (const float*)d_in[12];
    const float* emb    = (const float*)d_in[13];
    const float* W      = (const float*)d_in[14];
    float* out = (float*)d_out;

    float *pG, *pBias, *pHcat, *pHead, *pTail, *pShead, *pStail;
    cudaGetSymbolAddress((void**)&pG,     g_G);
    cudaGetSymbolAddress((void**)&pBias,  g_bias);
    cudaGetSymbolAddress((void**)&pHcat,  g_hcat);
    cudaGetSymbolAddress((void**)&pHead,  g_head);
    cudaGetSymbolAddress((void**)&pTail,  g_tail);
    cudaGetSymbolAddress((void**)&pShead, g_shead);
    cudaGetSymbolAddress((void**)&pStail, g_stail);

    cudaFuncSetAttribute(gemm_big,
                         cudaFuncAttributeMaxDynamicSharedMemorySize, GB_SMEM);

    prep_kernel<<<8, 256>>>(bih_f, bhh_f, bih_b, bhh_b, emb, W);

    // Stage 1: gate input projections, both directions in ONE launch (z)
    gemm_big<<<dim3(G4 / 128, ROWS / 128, 2), 256, GB_SMEM>>>(
        x, D_IN, Wih_f, Wih_b, D_IN,
        pBias, pBias + G4,
        pG, pG + (size_t)ROWS * G4, G4, D_IN, 0);

    // Stage 2: recurrence (st.async handoff)
    lstm_kernel<<<NGRP * CPG, 256>>>(Whh_f, Whh_b);

    // Stage 3: head + tail projections in ONE launch (z), leaky_relu
    gemm_big<<<dim3(MID / 128, ROWS / 128, 2), 256, GB_SMEM>>>(
        pHcat, MID, W_head, W_tail, MID,
        b_head, b_tail,
        pHead, pTail, MID, MID, 1);

    // Stage 4: biaffine projections (k=50), head+tail z-batched
    gemm_small<<<dim3(1, ROWS / 64, 2), 128>>>(
        pHead, pTail, MID, W, pShead, pStail, NOUT, NOUT, MID);

    // Stage 5: assemble 210MB output
    assemble_kernel<<<dim3(SEQ / 16, NOUT, NB), 256>>>(out);
}

// round 17
// speedup vs baseline: 2.4158x; 1.0498x over previous
#include <cuda_runtime.h>
#include <cstdint>

#define D_IN 1024
#define HID  256
#define G4   1024
#define MID  512
#define SEQ  512
#define NB   4
#define NOUT 50
#define SED  64
#define NPOS 30
#define WLD  1090           // 2*(MID+1) + SED
#define ROWS 2048           // NB*SEQ
#define CPG  8              // CTAs per recurrence group (== cluster size)
#define UPC  32             // hidden units per CTA
#define NGRP 8              // 2 dirs * 4 batch
#define HPAD 132            // floats per K-half (128 + 4 pad)
#define PSTR (2 * HPAD)     // floats per parity buffer

#define TROW 36             // smem floats per tile row (16B-aligned, conflict-free)
#define TSTR (128 * TROW)   // floats per tile
#define NSTG 3              // cp.async pipeline stages
#define GB_SMEM (NSTG * 2 * TSTR * 4)   // 110592 bytes

// ------------------------- scratch (static device memory) -------------------
__device__ float g_G[2][ROWS][G4];      // gate input preactivations (+bias)
__device__ float g_hcat[ROWS][MID];     // [b*SEQ+t][dir*HID + j]
__device__ float g_head[ROWS][MID];
__device__ float g_tail[ROWS][MID];
__device__ float g_shead[ROWS][NOUT];   // [(b,m)][k]
__device__ float g_stail[ROWS][NOUT];   // [(b,n)][k]

__device__ __forceinline__ float to_tf32(float x) {
    uint32_t u;
    asm("cvt.rna.tf32.f32 %0, %1;" : "=r"(u) : "f"(x));
    return __uint_as_float(u);
}
__device__ __forceinline__ uint32_t to_tf32u(float x) {
    uint32_t u;
    asm("cvt.rna.tf32.f32 %0, %1;" : "=r"(u) : "f"(x));
    return u;
}

// ------------------------- big tf32 GEMM: 3-stage cp.async ------------------
// C_z = A @ B_z^T + bias_z (+bias2_z) (opt leaky). 128x128 tiles, 256 thr.
__global__ void __launch_bounds__(256) gemm_big(
    const float* __restrict__ A, int lda,
    const float* __restrict__ B0, const float* __restrict__ B1, int ldb,
    const float* __restrict__ bias0, const float* __restrict__ bias1,
    const float* __restrict__ bias20, const float* __restrict__ bias21,
    float* __restrict__ C0, float* __restrict__ C1, int ldc,
    int K, int act)
{
    extern __shared__ float smem[];
    float* Asm = smem;                    // [NSTG][128][TROW]
    float* Bsm = smem + NSTG * TSTR;      // [NSTG][128][TROW]

    int z = blockIdx.z;
    const float* Bw    = z ? B1 : B0;
    const float* bias  = z ? bias1 : bias0;
    const float* bias2 = z ? bias21 : bias20;
    float* C = (z ? C1 : C0);

    int tid  = threadIdx.x;
    int warp = tid >> 5, lane = tid & 31;
    int gq = lane >> 2, tg = lane & 3;
    int wm = (warp >> 1) * 32, wn = (warp & 1) * 64;
    int bm = blockIdx.y * 128, bn = blockIdx.x * 128;

    uint32_t sa = (uint32_t)__cvta_generic_to_shared(Asm);
    uint32_t sb = (uint32_t)__cvta_generic_to_shared(Bsm);

    int nk = K >> 5;

    auto issue = [&](int stg, int k0) {
        #pragma unroll
        for (int i = 0; i < 4; i++) {
            int l4 = tid + i * 256;
            int r = l4 >> 3, c4 = (l4 & 7) << 2;
            uint32_t off = (uint32_t)(stg * TSTR + r * TROW + c4) * 4u;
            const float* pa = A  + (size_t)(bm + r) * lda + k0 + c4;
            const float* pb = Bw + (size_t)(bn + r) * ldb + k0 + c4;
            asm volatile("cp.async.cg.shared.global [%0], [%1], 16;"
                         :: "r"(sa + off), "l"(pa));
            asm volatile("cp.async.cg.shared.global [%0], [%1], 16;"
                         :: "r"(sb + off), "l"(pb));
        }
        asm volatile("cp.async.commit_group;" ::: "memory");
    };

    float acc[2][8][4];
    #pragma unroll
    for (int a = 0; a < 2; a++)
        #pragma unroll
        for (int b = 0; b < 8; b++)
            #pragma unroll
            for (int c = 0; c < 4; c++) acc[a][b][c] = 0.f;

    issue(0, 0);
    if (nk > 1) issue(1, 32);

    int stg = 0;
    for (int kc = 0; kc < nk; kc++) {
        if (kc + 2 < nk) {
            int s2 = stg + 2; if (s2 >= NSTG) s2 -= NSTG;
            issue(s2, (kc + 2) << 5);
            asm volatile("cp.async.wait_group 2;" ::: "memory");
        } else if (kc + 1 < nk) {
            asm volatile("cp.async.wait_group 1;" ::: "memory");
        } else {
            asm volatile("cp.async.wait_group 0;" ::: "memory");
        }
        __syncthreads();

        const float* At = Asm + stg * TSTR;
        const float* Bt = Bsm + stg * TSTR;

        #pragma unroll
        for (int kk = 0; kk < 32; kk += 8) {
            uint32_t af[2][4], bf[8][2];
            #pragma unroll
            for (int mf = 0; mf < 2; mf++) {
                int r0 = wm + mf * 16 + gq;
                af[mf][0] = to_tf32u(At[r0 * TROW + kk + tg]);
                af[mf][1] = to_tf32u(At[(r0 + 8) * TROW + kk + tg]);
                af[mf][2] = to_tf32u(At[r0 * TROW + kk + tg + 4]);
                af[mf][3] = to_tf32u(At[(r0 + 8) * TROW + kk + tg + 4]);
            }
            #pragma unroll
            for (int nf = 0; nf < 8; nf++) {
                int n0 = wn + nf * 8 + gq;
                bf[nf][0] = to_tf32u(Bt[n0 * TROW + kk + tg]);
                bf[nf][1] = to_tf32u(Bt[n0 * TROW + kk + tg + 4]);
            }
            #pragma unroll
            for (int mf = 0; mf < 2; mf++)
                #pragma unroll
                for (int nf = 0; nf < 8; nf++)
                    asm volatile(
                        "mma.sync.aligned.m16n8k8.row.col.f32.tf32.tf32.f32 "
                        "{%0,%1,%2,%3}, {%4,%5,%6,%7}, {%8,%9}, {%0,%1,%2,%3};\n"
                        : "+f"(acc[mf][nf][0]), "+f"(acc[mf][nf][1]),
                          "+f"(acc[mf][nf][2]), "+f"(acc[mf][nf][3])
                        : "r"(af[mf][0]), "r"(af[mf][1]), "r"(af[mf][2]), "r"(af[mf][3]),
                          "r"(bf[nf][0]), "r"(bf[nf][1]));
        }
        __syncthreads();
        if (++stg == NSTG) stg = 0;
    }

    #pragma unroll
    for (int mf = 0; mf < 2; mf++) {
        #pragma unroll
        for (int nf = 0; nf < 8; nf++) {
            int row = bm + wm + mf * 16 + gq;
            int col = bn + wn + nf * 8 + tg * 2;
            #pragma unroll
            for (int q = 0; q < 4; q++) {
                int r = row + (q >> 1) * 8;
                int c = col + (q & 1);
                float v = acc[mf][nf][q] + bias[c];
                if (bias2) v += bias2[c];
                if (act) v = v > 0.f ? v : 0.01f * v;
                C[(size_t)r * ldc + c] = v;
            }
        }
    }
}

// ------------------------- small tf32 GEMM (stage 4, N=50, z-batched) -------
__global__ void __launch_bounds__(128) gemm_small(
    const float* __restrict__ A0, const float* __restrict__ A1, int lda,
    const float* __restrict__ W,
    float* __restrict__ C0, float* __restrict__ C1, int ldc,
    int N, int K)
{
    __shared__ float As[64][33];
    __shared__ float Bs[64][33];
    int z = blockIdx.z;
    const float* A    = z ? A1 : A0;
    const float* Bw   = W + (size_t)z * (MID + 1);
    const float* bias = Bw + MID;

    float* C = z ? C1 : C0;

    int tid  = threadIdx.x;
    int warp = tid >> 5, lane = tid & 31;
    int gq = lane >> 2, tg = lane & 3;
    int wm = (warp >> 1) * 32, wn = (warp & 1) * 32;
    int bm = blockIdx.y * 64, bn = 0;

    float acc[2][4][4];
    #pragma unroll
    for (int a = 0; a < 2; a++)
        #pragma unroll
        for (int b = 0; b < 4; b++)
            #pragma unroll
            for (int c = 0; c < 4; c++) acc[a][b][c] = 0.f;

    for (int k0 = 0; k0 < K; k0 += 32) {
        #pragma unroll
        for (int i = 0; i < 4; i++) {
            int l4 = tid + i * 128;
            int r = l4 >> 3, c4 = (l4 & 7) << 2;
            const float4 v = *reinterpret_cast<const float4*>(A + (size_t)(bm + r) * lda + k0 + c4);
            As[r][c4 + 0] = to_tf32(v.x); As[r][c4 + 1] = to_tf32(v.y);
            As[r][c4 + 2] = to_tf32(v.z); As[r][c4 + 3] = to_tf32(v.w);
        }
        #pragma unroll
        for (int i = 0; i < 4; i++) {
            int l4 = tid + i * 128;
            int r = l4 >> 3, c4 = (l4 & 7) << 2;
            float4 v = make_float4(0.f, 0.f, 0.f, 0.f);
            if (bn + r < N) {
                const float* p = Bw + (size_t)(bn + r) * WLD + k0 + c4;
                v = make_float4(p[0], p[1], p[2], p[3]);
            }
            Bs[r][c4 + 0] = to_tf32(v.x); Bs[r][c4 + 1] = to_tf32(v.y);
            Bs[r][c4 + 2] = to_tf32(v.z); Bs[r][c4 + 3] = to_tf32(v.w);
        }
        __syncthreads();

        #pragma unroll
        for (int kk = 0; kk < 32; kk += 8) {
            uint32_t af[2][4], bf[4][2];
            #pragma unroll
            for (int mf = 0; mf < 2; mf++) {
                int r0 = wm + mf * 16 + gq;
                af[mf][0] = __float_as_uint(As[r0    ][kk + tg]);
                af[mf][1] = __float_as_uint(As[r0 + 8][kk + tg]);
                af[mf][2] = __float_as_uint(As[r0    ][kk + tg + 4]);
                af[mf][3] = __float_as_uint(As[r0 + 8][kk + tg + 4]);
            }
            #pragma unroll
            for (int nf = 0; nf < 4; nf++) {
                int n0 = wn + nf * 8 + gq;
                bf[nf][0] = __float_as_uint(Bs[n0][kk + tg]);
                bf[nf][1] = __float_as_uint(Bs[n0][kk + tg + 4]);
            }
            #pragma unroll
            for (int mf = 0; mf < 2; mf++)
                #pragma unroll
                for (int nf = 0; nf < 4; nf++)
                    asm volatile(
                        "mma.sync.aligned.m16n8k8.row.col.f32.tf32.tf32.f32 "
                        "{%0,%1,%2,%3}, {%4,%5,%6,%7}, {%8,%9}, {%0,%1,%2,%3};\n"
                        : "+f"(acc[mf][nf][0]), "+f"(acc[mf][nf][1]),
                          "+f"(acc[mf][nf][2]), "+f"(acc[mf][nf][3])
                        : "r"(af[mf][0]), "r"(af[mf][1]), "r"(af[mf][2]), "r"(af[mf][3]),
                          "r"(bf[nf][0]), "r"(bf[nf][1]));
        }
        __syncthreads();
    }

    #pragma unroll
    for (int mf = 0; mf < 2; mf++) {
        #pragma unroll
        for (int nf = 0; nf < 4; nf++) {
            int row = bm + wm + mf * 16 + gq;
            int col = bn + wn + nf * 8 + tg * 2;
            #pragma unroll
            for (int q = 0; q < 4; q++) {
                int r = row + (q >> 1) * 8;
                int c = col + (q & 1);
                if (c < N)
                    C[(size_t)r * ldc + c] = acc[mf][nf][q] + bias[(size_t)c * WLD];
            }
        }
    }
}

// ------------------------- LSTM recurrence (st.async handoff) ---------------
__device__ __forceinline__ float sigm(float x) { return 1.f / (1.f + __expf(-x)); }
__device__ __forceinline__ float ftanh(float x) {
    float e = __expf(2.f * x);
    return 1.f - __fdividef(2.f, e + 1.f);
}
__device__ __forceinline__ void fma2(unsigned long long& acc,
                                     unsigned long long a, unsigned long long b) {
    asm("fma.rn.f32x2 %0, %1, %2, %0;" : "+l"(acc) : "l"(a), "l"(b));
}
__device__ __forceinline__ void add2(unsigned long long& a, unsigned long long b) {
    asm("add.rn.f32x2 %0, %0, %1;" : "+l"(a) : "l"(b));
}
__device__ __forceinline__ float pairsum(unsigned long long p) {
    uint32_t lo, hi;
    asm("mov.b64 {%0,%1}, %2;" : "=r"(lo), "=r"(hi) : "l"(p));
    return __uint_as_float(lo) + __uint_as_float(hi);
}

__global__ void __launch_bounds__(256, 1) __cluster_dims__(CPG, 1, 1)
lstm_kernel(const float* __restrict__ Whh_f, const float* __restrict__ Whh_b)
{
    __shared__ __align__(16) float    hs2[2][PSTR];
    __shared__ __align__(16) float    red[2][128];
    __shared__ __align__(16) float    hstage[2][UPC];
    __shared__ __align__(8)  unsigned long long mbar[2];

    int grp = blockIdx.x / CPG;
    uint32_t cig;
    asm("mov.u32 %0, %%cluster_ctarank;" : "=r"(cig));
    int d = grp >> 2, b = grp & 3;
    int tid  = threadIdx.x;
    int w    = tid >> 5;
    int lane = tid & 31;
    int row  = w * 16 + (lane & 15);
    int kh   = lane >> 4;
    int gi   = row >> 5;
    int ul   = row & 31;
    int j    = (int)cig * UPC + ul;
    int grow = gi * HID + j;
    const float* Whh = d ? Whh_b : Whh_f;
    const float* Gd  = &g_G[d][0][0];

    ulonglong2 w2[32];
    #pragma unroll
    for (int q = 0; q < 32; q++)
        w2[q] = *reinterpret_cast<const ulonglong2*>(
            &Whh[(size_t)grow * HID + kh * 128 + q * 4]);

    uint32_t mbar_u32 = (uint32_t)__cvta_generic_to_shared(&mbar[0]);
    for (int i = tid; i < 2 * PSTR; i += 256) ((float*)hs2)[i] = 0.f;
    if (tid < 2)
        asm volatile("mbarrier.init.shared.b64 [%0], %1;"
                     :: "r"(mbar_u32 + tid * 8u), "r"(1) : "memory");
    __syncthreads();
    asm volatile("barrier.cluster.arrive.aligned;" ::: "memory");
    asm volatile("barrier.cluster.wait.aligned;"  ::: "memory");

    uint32_t hs_u32 = (uint32_t)__cvta_generic_to_shared(&hs2[0][0]);

    int ds = (int)cig * UPC + ((int)cig >= 4 ? 4 : 0);
    uint32_t ra[2], rm[2];
    {
        int rnk = (lane >> 2) & 7, seg = lane & 3;
        #pragma unroll
        for (int P = 0; P < 2; P++) {
            uint32_t laddr = hs_u32 + (uint32_t)(P * PSTR + ds) * 4u + (uint32_t)seg * 32u;
            asm("mapa.shared::cluster.u32 %0, %1, %2;"
                : "=r"(ra[P]) : "r"(laddr), "r"(rnk));
            asm("mapa.shared::cluster.u32 %0, %1, %2;"
                : "=r"(rm[P]) : "r"(mbar_u32 + (uint32_t)P * 8u), "r"(rnk));
        }
    }

    float cst = 0.f;
    uint32_t ph0 = 0, ph1 = 0;

    for (int st = 0; st < SEQ; st++) {
        int t = d ? (SEQ - 1 - st) : st;
        int cur = st & 1, nxt = cur ^ 1;

        float gin = 0.f;
        if (kh == 0)
            gin = __ldg(&Gd[(size_t)(b * SEQ + t) * G4 + grow]);

        if (st > 0) {
            uint32_t mb  = mbar_u32 + (uint32_t)cur * 8u;
            uint32_t par = cur ? ph1 : ph0;
            asm volatile(
                "{.reg .pred P1;\n\t"
                "LAB_%=: mbarrier.try_wait.parity.acquire.cluster.shared::cta.b64 P1, [%0], %1, 0x989680;\n\t"
                "@P1 bra DONE_%=;\n\t"
                "bra LAB_%=;\n\t"
                "DONE_%=:}\n"
                :: "r"(mb), "r"(par) : "memory");
            if (cur) ph1 ^= 1; else ph0 ^= 1;
        }

        // arm next parity's mbarrier EARLY (off warp0's post-barrier chain).
        // mbar[nxt]'s prior phase completed at step st-1; tx-before-expect is
        // balanced by mbarrier tx-count semantics.
        if (w == 0 && lane == 0 && st < SEQ - 1)
            asm volatile("mbarrier.arrive.expect_tx.shared.b64 _, [%0], %1;"
                         :: "r"(mbar_u32 + (uint32_t)nxt * 8u), "r"(1024) : "memory");

        if (w == 1 && st > 0) {
            int tp = d ? (SEQ - st) : (st - 1);
            g_hcat[b * SEQ + tp][d * HID + (int)cig * UPC + lane] = hstage[(st - 1) & 1][lane];
        }

        const float* hb = &hs2[cur][kh * HPAD];
        unsigned long long acc[4] = {0ull, 0ull, 0ull, 0ull};
        #pragma unroll
        for (int q = 0; q < 32; q++) {
            const ulonglong2 hv = *reinterpret_cast<const ulonglong2*>(hb + q * 4);
            fma2(acc[q & 3], w2[q].x, hv.x);
            fma2(acc[q & 3], w2[q].y, hv.y);
        }
        add2(acc[0], acc[2]); add2(acc[1], acc[3]); add2(acc[0], acc[1]);
        float s = pairsum(acc[0]);
        s += __shfl_xor_sync(0xffffffffu, s, 16);
        if (kh == 0) {
            float pre = s + gin;
            red[cur][row] = (gi == 2) ? ftanh(pre) : sigm(pre);
        }

        if (w != 0) {
            asm volatile("bar.arrive 1, 256;" ::: "memory");
        } else {
            asm volatile("bar.sync 1, 256;" ::: "memory");
            float iv = red[cur][lane],      fv = red[cur][32 + lane];
            float gv = red[cur][64 + lane], ov = red[cur][96 + lane];
            cst = fv * cst + iv * gv;
            float h = ov * ftanh(cst);
            hstage[cur][lane] = h;
            __syncwarp();
            if (st < SEQ - 1) {
                int seg = lane & 3;
                const ulonglong2* sp = reinterpret_cast<const ulonglong2*>(&hstage[cur][0]) + seg * 2;
                ulonglong2 v0 = sp[0], v1 = sp[1];
                uint32_t dst = ra[nxt], mbr = rm[nxt];
                asm volatile("st.async.shared::cluster.mbarrier::complete_tx::bytes.b64 [%0], %1, [%2];"
                             :: "r"(dst      ), "l"(v0.x), "r"(mbr) : "memory");
                asm volatile("st.async.shared::cluster.mbarrier::complete_tx::bytes.b64 [%0], %1, [%2];"
                             :: "r"(dst +  8u), "l"(v0.y), "r"(mbr) : "memory");
                asm volatile("st.async.shared::cluster.mbarrier::complete_tx::bytes.b64 [%0], %1, [%2];"
                             :: "r"(dst + 16u), "l"(v1.x), "r"(mbr) : "memory");
                asm volatile("st.async.shared::cluster.mbarrier::complete_tx::bytes.b64 [%0], %1, [%2];"
                             :: "r"(dst + 24u), "l"(v1.y), "r"(mbr) : "memory");
            }
        }
    }

    __syncthreads();
    if (w == 1) {
        int tp = d ? 0 : (SEQ - 1);
        g_hcat[b * SEQ + tp][d * HID + (int)cig * UPC + lane] = hstage[(SEQ - 1) & 1][lane];
    }

    asm volatile("barrier.cluster.arrive.aligned;" ::: "memory");
    asm volatile("barrier.cluster.wait.aligned;"  ::: "memory");
}

// ------------------------- final assembly (sztab computed inline) -----------
// out[b][k][m][n] = s_head[b,k,m] + s_tail[b,k,n] + sztab[k][clamp(n-m)]
__global__ void __launch_bounds__(256) assemble_kernel(
    float* __restrict__ out,
    const float* __restrict__ emb, const float* __restrict__ W)
{
    int b = blockIdx.z, k = blockIdx.y, m0 = blockIdx.x * 16;
    int tid = threadIdx.x;
    __shared__ float st_s[SEQ];
    __shared__ float sz_s[NPOS];
    __shared__ float sh_s[16];
    for (int i = tid; i < SEQ; i += 256) st_s[i] = g_stail[b * SEQ + i][k];
    if (tid < NPOS) {
        const float* ep = emb + tid * SED;
        const float* wp = W + (size_t)k * WLD + 2 * (MID + 1);
        float s = 0.f;
        #pragma unroll 8
        for (int h = 0; h < SED; h++) s += ep[h] * wp[h];
        sz_s[tid] = s;
    }
    if (tid < 16)   sh_s[tid] = g_shead[b * SEQ + m0 + tid][k];
    __syncthreads();

    float* orow = out + (((size_t)(b * NOUT + k)) * SEQ + m0) * SEQ;
    #pragma unroll
    for (int it = 0; it < 8; it++) {
        int lin = it * 256 + tid;
        int r = lin >> 7;
        int n4 = (lin & 127) << 2;
        int m = m0 + r;
        float sh = sh_s[r];
        float4 v;
        int e;
        e = min(max(n4     - m, -15), 14) + 15; v.x = sh + st_s[n4    ] + sz_s[e];
        e = min(max(n4 + 1 - m, -15), 14) + 15; v.y = sh + st_s[n4 + 1] + sz_s[e];
        e = min(max(n4 + 2 - m, -15), 14) + 15; v.z = sh + st_s[n4 + 2] + sz_s[e];
        e = min(max(n4 + 3 - m, -15), 14) + 15; v.w = sh + st_s[n4 + 3] + sz_s[e];
        *reinterpret_cast<float4*>(orow + (size_t)r * SEQ + n4) = v;
    }
}

// ------------------------- launch -------------------------------------------
extern "C" void kernel_launch(void* const* d_in, const int* in_sizes, int n_in,
                              void* d_out, int out_size)
{
    const float* x      = (const float*)d_in[0];
    const float* Wih_f  = (const float*)d_in[1];
    const float* Whh_f  = (const float*)d_in[2];
    const float* bih_f  = (const float*)d_in[3];
    const float* bhh_f  = (const float*)d_in[4];
    const float* Wih_b  = (const float*)d_in[5];
    const float* Whh_b  = (const float*)d_in[6];
    const float* bih_b  = (const float*)d_in[7];
    const float* bhh_b  = (const float*)d_in[8];
    const float* W_head = (const float*)d_in[9];
    const float* b_head = (const float*)d_in[10];
    const float* W_tail = (const float*)d_in[11];
    const float* b_tail = (const float*)d_in[12];
    const float* emb    = (const float*)d_in[13];
    const float* W      = (const float*)d_in[14];
    float* out = (float*)d_out;

    float *pG, *pHcat, *pHead, *pTail, *pShead, *pStail;
    cudaGetSymbolAddress((void**)&pG,     g_G);
    cudaGetSymbolAddress((void**)&pHcat,  g_hcat);
    cudaGetSymbolAddress((void**)&pHead,  g_head);
    cudaGetSymbolAddress((void**)&pTail,  g_tail);
    cudaGetSymbolAddress((void**)&pShead, g_shead);
    cudaGetSymbolAddress((void**)&pStail, g_stail);

    cudaFuncSetAttribute(gemm_big,
                         cudaFuncAttributeMaxDynamicSharedMemorySize, GB_SMEM);

    // Stage 1: gate input projections, both directions; bias = bih+bhh inline
    gemm_big<<<dim3(G4 / 128, ROWS / 128, 2), 256, GB_SMEM>>>(
        x, D_IN, Wih_f, Wih_b, D_IN,
        bih_f, bih_b, bhh_f, bhh_b,
        pG, pG + (size_t)ROWS * G4, G4, D_IN, 0);

    // Stage 2: recurrence (st.async handoff)
    lstm_kernel<<<NGRP * CPG, 256>>>(Whh_f, Whh_b);

    // Stage 3: head + tail projections, leaky_relu
    gemm_big<<<dim3(MID / 128, ROWS / 128, 2), 256, GB_SMEM>>>(
        pHcat, MID, W_head, W_tail, MID,
        b_head, b_tail, nullptr, nullptr,
        pHead, pTail, MID, MID, 1);

    // Stage 4: biaffine projections (k=50), head+tail z-batched
    gemm_small<<<dim3(1, ROWS / 64, 2), 128>>>(
        pHead, pTail, MID, W, pShead, pStail, NOUT, NOUT, MID);

    // Stage 5: assemble 210MB output (sztab computed inline)
    assemble_kernel<<<dim3(SEQ / 16, NOUT, NB), 256>>>(out, emb, W);
}